// round 3
// baseline (speedup 1.0000x reference)
#include <cuda_runtime.h>
#include <cstdint>
#include <cstddef>

#define Bdim 64
#define Sdim 512
#define Idim 128
#define Hdim 2048
#define Odim 128
#define ALPHA 0.2f
#define NSTD  0.005f

__device__ float g_Wt[(size_t)Hdim * Hdim];              // ALPHA*g[k]*wrec[j][k], [j][k]
__device__ float g_hist[(size_t)Sdim * Bdim * Hdim];     // h_t, [t][b][k]
__device__ float g_xp[(size_t)(Sdim - 1) * Bdim * Hdim]; // NSTD*noise + ALPHA*x@wi, [t][b][j]

typedef unsigned long long u64;

__device__ __forceinline__ u64 ffma2(u64 a, u64 b, u64 c) {
    u64 d;
    asm("fma.rn.f32x2 %0, %1, %2, %3;" : "=l"(d) : "l"(a), "l"(b), "l"(c));
    return d;
}
__device__ __forceinline__ float hsum2(u64 a) {
    float2 f = *reinterpret_cast<float2*>(&a);
    return f.x + f.y;
}

// ---------------------------------------------------------------------------
__global__ void prep_kernel(const float* __restrict__ wrec,
                            const float* __restrict__ g,
                            const float* __restrict__ h0) {
    int j = blockIdx.x;
    const float* wr = wrec + (size_t)j * Hdim;
    float* wt = g_Wt + (size_t)j * Hdim;
    for (int k = threadIdx.x; k < Hdim; k += blockDim.x)
        wt[k] = ALPHA * g[k] * wr[k];
    if (j < Bdim) {
        float* h = g_hist + (size_t)j * Hdim;
        for (int k = threadIdx.x; k < Hdim; k += blockDim.x)
            h[k] = h0[k];
    }
}

// ---------------------------------------------------------------------------
// xp: xp[t][b][j] = NSTD*noise[b][t][j] + ALPHA * sum_i x[b][t][i]*wi[i][j]
// ---------------------------------------------------------------------------
__global__ void xp_kernel(const float* __restrict__ x,
                          const float* __restrict__ noise,
                          const float* __restrict__ wi) {
    __shared__ float sx[64][68];
    __shared__ float sw[64][68];
    int t  = blockIdx.y;
    int c0 = blockIdx.x * 64;
    int tid = threadIdx.x;
    int tx = tid & 15, ty = tid >> 4;

    u64 acc[4][4];
    #pragma unroll
    for (int i = 0; i < 4; i++)
        #pragma unroll
        for (int j = 0; j < 4; j++) acc[i][j] = 0ull;

    for (int k0 = 0; k0 < Idim; k0 += 64) {
        #pragma unroll
        for (int i = 0; i < 4; i++) {
            int idx = tid + 256 * i;
            int b = idx >> 4, q = idx & 15;
            float4 v = *(const float4*)(x + ((size_t)b * Sdim + t) * Idim + k0 + q * 4);
            *(float4*)&sx[b][q * 4] = v;
        }
        #pragma unroll
        for (int i = 0; i < 4; i++) {
            int idx = tid + 256 * i;
            int kr = idx >> 4, q = idx & 15;
            float4 v = *(const float4*)(wi + ((size_t)(k0 + kr)) * Hdim + c0 + q * 4);
            sw[q * 4 + 0][kr] = v.x;
            sw[q * 4 + 1][kr] = v.y;
            sw[q * 4 + 2][kr] = v.z;
            sw[q * 4 + 3][kr] = v.w;
        }
        __syncthreads();
        #pragma unroll
        for (int kb = 0; kb < 64; kb += 2) {
            u64 ha[4], wb[4];
            #pragma unroll
            for (int i = 0; i < 4; i++) ha[i] = *(const u64*)&sx[ty + 16 * i][kb];
            #pragma unroll
            for (int j = 0; j < 4; j++) wb[j] = *(const u64*)&sw[tx + 16 * j][kb];
            #pragma unroll
            for (int i = 0; i < 4; i++)
                #pragma unroll
                for (int j = 0; j < 4; j++)
                    acc[i][j] = ffma2(ha[i], wb[j], acc[i][j]);
        }
        __syncthreads();
    }

    #pragma unroll
    for (int i = 0; i < 4; i++) {
        int b = ty + 16 * i;
        #pragma unroll
        for (int j = 0; j < 4; j++) {
            int jc = c0 + tx + 16 * j;
            float s = hsum2(acc[i][j]);
            float n = noise[((size_t)b * Sdim + t) * Hdim + jc];
            g_xp[((size_t)t * Bdim + b) * Hdim + jc] = NSTD * n + ALPHA * s;
        }
    }
}

// ---------------------------------------------------------------------------
// step t: hout[b][j] = 0.8*hin[b][j] + sum_k hin[b][k]*Wt[j][k] + xp[t][b][j]
// grid 128 CTAs (j-tile 16), 512 threads (16 warps, warp = K/16 slice).
// lane -> b in {lane, lane+32}; accs 2b x 16j as f32x2 along k.
// Double-buffered 128-k slabs in dynamic smem; w reads are warp-broadcast LDS.
// ---------------------------------------------------------------------------
#define SLAB 128
#define PITCH 132                       // floats; 528B, 16B-aligned, odd u128 stride
#define HSLAB (64 * PITCH)
#define WSLAB (16 * PITCH)
#define WOFF  (2 * HSLAB)
#define SMEM_STEP ((2 * HSLAB + 2 * WSLAB) * 4)   // 84480 bytes

extern __shared__ float SH[];

__global__ void __launch_bounds__(512, 1) step_kernel(int t) {
    int tid = threadIdx.x;
    int warp = tid >> 5, lane = tid & 31;
    int c0 = blockIdx.x * 16;
    const float* hin = g_hist + (size_t)t * Bdim * Hdim;
    const float* wbase = g_Wt + (size_t)c0 * Hdim;

    u64 acc[2][16];
    #pragma unroll
    for (int i = 0; i < 2; i++)
        #pragma unroll
        for (int j = 0; j < 16; j++) acc[i][j] = 0ull;

    // staging index: thread handles h rows {hr, hr+16, hr+32, hr+48} at col hc,
    // and w row wr=warp at col hc. All coalesced LDG.128.
    int hr = tid >> 5;            // 0..15
    int hc = (tid & 31) * 4;      // 0..124

    // stage slab 0 into buf 0
    {
        #pragma unroll
        for (int i = 0; i < 4; i++) {
            float4 v = *(const float4*)(hin + (size_t)(hr + 16 * i) * Hdim + hc);
            *(float4*)&SH[(hr + 16 * i) * PITCH + hc] = v;
        }
        float4 wv = *(const float4*)(wbase + (size_t)hr * Hdim + hc);
        *(float4*)&SH[WOFF + hr * PITCH + hc] = wv;
    }
    __syncthreads();

    int ks = warp * 8;   // this warp's k-offset within a slab
    for (int s = 0; s < Hdim / SLAB; s++) {
        int buf = s & 1;
        float4 ph[4], pw;
        if (s + 1 < Hdim / SLAB) {
            int k0 = (s + 1) * SLAB;
            #pragma unroll
            for (int i = 0; i < 4; i++)
                ph[i] = *(const float4*)(hin + (size_t)(hr + 16 * i) * Hdim + k0 + hc);
            pw = *(const float4*)(wbase + (size_t)hr * Hdim + k0 + hc);
        }

        const float* hb = SH + buf * HSLAB + lane * PITCH + ks;
        ulonglong2 a00 = *(const ulonglong2*)(hb);
        ulonglong2 a01 = *(const ulonglong2*)(hb + 4);
        ulonglong2 a10 = *(const ulonglong2*)(hb + 32 * PITCH);
        ulonglong2 a11 = *(const ulonglong2*)(hb + 32 * PITCH + 4);
        const float* wp = SH + WOFF + buf * WSLAB + ks;
        #pragma unroll
        for (int j = 0; j < 16; j++) {
            ulonglong2 w0 = *(const ulonglong2*)(wp + j * PITCH);
            ulonglong2 w1 = *(const ulonglong2*)(wp + j * PITCH + 4);
            acc[0][j] = ffma2(a00.x, w0.x, acc[0][j]);
            acc[0][j] = ffma2(a00.y, w0.y, acc[0][j]);
            acc[0][j] = ffma2(a01.x, w1.x, acc[0][j]);
            acc[0][j] = ffma2(a01.y, w1.y, acc[0][j]);
            acc[1][j] = ffma2(a10.x, w0.x, acc[1][j]);
            acc[1][j] = ffma2(a10.y, w0.y, acc[1][j]);
            acc[1][j] = ffma2(a11.x, w1.x, acc[1][j]);
            acc[1][j] = ffma2(a11.y, w1.y, acc[1][j]);
        }
        __syncthreads();
        if (s + 1 < Hdim / SLAB) {
            int nb = buf ^ 1;
            #pragma unroll
            for (int i = 0; i < 4; i++)
                *(float4*)&SH[nb * HSLAB + (hr + 16 * i) * PITCH + hc] = ph[i];
            *(float4*)&SH[WOFF + nb * WSLAB + hr * PITCH + hc] = pw;
        }
        __syncthreads();
    }

    // ---- cross-warp reduction (16 partials per output) via smem tree ----
    // red layout: red[entry*128 + slot*32 + lane], entry in [0,32), slot in [0,4)
    float2* red = (float2*)SH;   // 32KB region, aliases slab buffers (safe: bar'd)

    #define STASH(SLOT)                                                     \
        {                                                                   \
            float2* p = red + (SLOT) * 32 + lane;                           \
            _Pragma("unroll")                                               \
            for (int i = 0; i < 2; i++)                                     \
                _Pragma("unroll")                                           \
                for (int j = 0; j < 16; j++)                                \
                    p[(i * 16 + j) * 128] = *(float2*)&acc[i][j];           \
        }
    #define GATHER(SLOT)                                                    \
        {                                                                   \
            float2* p = red + (SLOT) * 32 + lane;                           \
            _Pragma("unroll")                                               \
            for (int i = 0; i < 2; i++)                                     \
                _Pragma("unroll")                                           \
                for (int j = 0; j < 16; j++) {                              \
                    float2 v = p[(i * 16 + j) * 128];                       \
                    float2* a = (float2*)&acc[i][j];                        \
                    a->x += v.x; a->y += v.y;                               \
                }                                                           \
        }

    if (warp >= 8 && warp < 12) STASH(warp - 8);
    __syncthreads();
    if (warp < 4) GATHER(warp);
    __syncthreads();
    if (warp >= 12) STASH(warp - 12);
    __syncthreads();
    if (warp >= 4 && warp < 8) GATHER(warp - 4);
    __syncthreads();
    if (warp >= 4 && warp < 8) STASH(warp - 4);
    __syncthreads();
    if (warp < 4) GATHER(warp);
    __syncthreads();
    if (warp >= 2 && warp < 4) STASH(warp - 2);
    __syncthreads();
    if (warp < 2) GATHER(warp);
    __syncthreads();
    if (warp == 1) STASH(0);
    __syncthreads();

    if (warp == 0) {
        GATHER(0);
        const float* xp = g_xp + (size_t)t * Bdim * Hdim;
        float* hout = g_hist + (size_t)(t + 1) * Bdim * Hdim;
        #pragma unroll
        for (int i = 0; i < 2; i++) {
            int b = lane + 32 * i;
            const float* hrp = hin + (size_t)b * Hdim + c0;
            const float* xrp = xp + (size_t)b * Hdim + c0;
            float* orp = hout + (size_t)b * Hdim + c0;
            #pragma unroll
            for (int q = 0; q < 4; q++) {
                float4 hv = *(const float4*)(hrp + q * 4);
                float4 xv = *(const float4*)(xrp + q * 4);
                float4 o;
                o.x = (1.0f - ALPHA) * hv.x + hsum2(acc[i][q * 4 + 0]) + xv.x;
                o.y = (1.0f - ALPHA) * hv.y + hsum2(acc[i][q * 4 + 1]) + xv.y;
                o.z = (1.0f - ALPHA) * hv.z + hsum2(acc[i][q * 4 + 2]) + xv.z;
                o.w = (1.0f - ALPHA) * hv.w + hsum2(acc[i][q * 4 + 3]) + xv.w;
                *(float4*)(orp + q * 4) = o;
            }
        }
    }
}

// ---------------------------------------------------------------------------
// out: out[b][t][o] = sum_k hist[t][b][k] * wout[k][o]
// ---------------------------------------------------------------------------
__global__ void out_kernel(const float* __restrict__ wout,
                           float* __restrict__ out) {
    __shared__ float sh[64][68];
    __shared__ float sw[64][68];
    int t  = blockIdx.y;
    int c0 = blockIdx.x * 64;
    int tid = threadIdx.x;
    int tx = tid & 15, ty = tid >> 4;

    u64 acc[4][4];
    #pragma unroll
    for (int i = 0; i < 4; i++)
        #pragma unroll
        for (int j = 0; j < 4; j++) acc[i][j] = 0ull;

    const float* hin = g_hist + (size_t)t * Bdim * Hdim;

    for (int k0 = 0; k0 < Hdim; k0 += 64) {
        #pragma unroll
        for (int i = 0; i < 4; i++) {
            int idx = tid + 256 * i;
            int b = idx >> 4, q = idx & 15;
            *(float4*)&sh[b][q * 4] = *(const float4*)(hin + (size_t)b * Hdim + k0 + q * 4);
        }
        #pragma unroll
        for (int i = 0; i < 4; i++) {
            int idx = tid + 256 * i;
            int kr = idx >> 4, q = idx & 15;
            float4 v = *(const float4*)(wout + ((size_t)(k0 + kr)) * Odim + c0 + q * 4);
            sw[q * 4 + 0][kr] = v.x;
            sw[q * 4 + 1][kr] = v.y;
            sw[q * 4 + 2][kr] = v.z;
            sw[q * 4 + 3][kr] = v.w;
        }
        __syncthreads();
        #pragma unroll
        for (int kb = 0; kb < 64; kb += 2) {
            u64 ha[4], wb[4];
            #pragma unroll
            for (int i = 0; i < 4; i++) ha[i] = *(const u64*)&sh[ty + 16 * i][kb];
            #pragma unroll
            for (int j = 0; j < 4; j++) wb[j] = *(const u64*)&sw[tx + 16 * j][kb];
            #pragma unroll
            for (int i = 0; i < 4; i++)
                #pragma unroll
                for (int j = 0; j < 4; j++)
                    acc[i][j] = ffma2(ha[i], wb[j], acc[i][j]);
        }
        __syncthreads();
    }

    #pragma unroll
    for (int i = 0; i < 4; i++) {
        int b = ty + 16 * i;
        #pragma unroll
        for (int j = 0; j < 4; j++) {
            int o = c0 + tx + 16 * j;
            out[((size_t)b * Sdim + t) * Odim + o] = hsum2(acc[i][j]);
        }
    }
}

// ---------------------------------------------------------------------------
extern "C" void kernel_launch(void* const* d_in, const int* in_sizes, int n_in,
                              void* d_out, int out_size) {
    const float* x     = (const float*)d_in[0];
    const float* noise = (const float*)d_in[1];
    const float* wi    = (const float*)d_in[2];
    const float* wrec  = (const float*)d_in[3];
    const float* wout  = (const float*)d_in[4];
    const float* g     = (const float*)d_in[5];
    const float* h0    = (const float*)d_in[6];
    float* out = (float*)d_out;

    cudaFuncSetAttribute(step_kernel, cudaFuncAttributeMaxDynamicSharedMemorySize,
                         SMEM_STEP);

    prep_kernel<<<Hdim, 256>>>(wrec, g, h0);
    xp_kernel<<<dim3(Hdim / 64, Sdim - 1), 256>>>(x, noise, wi);
    for (int t = 0; t < Sdim - 1; t++)
        step_kernel<<<Hdim / 16, 512, SMEM_STEP>>>(t);
    out_kernel<<<dim3(Odim / 64, Sdim), 256>>>(wout, out);
}

// round 10
// speedup vs baseline: 2.4711x; 2.4711x over previous
#include <cuda_runtime.h>
#include <cuda_bf16.h>
#include <cstdint>
#include <cstddef>

#define Bdim 64
#define Sdim 512
#define Idim 128
#define Hdim 2048
#define Odim 128
#define ALPHA 0.2f
#define NSTD  0.005f

// ---- device scratch ----
__device__ __nv_bfloat16 g_Whi[(size_t)Hdim * Hdim];      // bf16 hi of ALPHA*g[k]*wrec[j][k]
__device__ __nv_bfloat16 g_Wlo[(size_t)Hdim * Hdim];      // bf16 lo residual
__device__ __nv_bfloat16 g_hh[2][(size_t)Bdim * Hdim];    // h hi, parity by t
__device__ __nv_bfloat16 g_hl[2][(size_t)Bdim * Hdim];    // h lo
__device__ float g_hist[(size_t)Sdim * Bdim * Hdim];      // h_t fp32, [t][b][k]
__device__ float g_xp[(size_t)(Sdim - 1) * Bdim * Hdim];  // NSTD*noise + ALPHA*x@wi
__device__ float g_part[8][(size_t)Bdim * Hdim];          // k-split partials
__device__ unsigned g_cnt[16];                            // per-j-tile arrival counters

typedef unsigned long long u64;
typedef unsigned int u32;

__device__ __forceinline__ u64 ffma2(u64 a, u64 b, u64 c) {
    u64 d;
    asm("fma.rn.f32x2 %0, %1, %2, %3;" : "=l"(d) : "l"(a), "l"(b), "l"(c));
    return d;
}
__device__ __forceinline__ float hsum2(u64 a) {
    float2 f = *reinterpret_cast<float2*>(&a);
    return f.x + f.y;
}

__device__ __forceinline__ u32 s2u(const void* p) {
    return (u32)__cvta_generic_to_shared(p);
}
__device__ __forceinline__ void cp16(u32 dst, const void* src) {
    asm volatile("cp.async.cg.shared.global [%0], [%1], 16;" :: "r"(dst), "l"(src));
}
#define CPCOMMIT() asm volatile("cp.async.commit_group;")
#define CPWAIT(N)  asm volatile("cp.async.wait_group " #N ";")

#define LDSM4(R, ADDR)                                                        \
    asm volatile("ldmatrix.sync.aligned.m8n8.x4.shared.b16 {%0,%1,%2,%3},[%4];" \
                 : "=r"((R)[0]), "=r"((R)[1]), "=r"((R)[2]), "=r"((R)[3])     \
                 : "r"(ADDR))

#define MMA16816(C, A, B0, B1)                                                \
    asm volatile("mma.sync.aligned.m16n8k16.row.col.f32.bf16.bf16.f32 "       \
                 "{%0,%1,%2,%3},{%4,%5,%6,%7},{%8,%9},{%0,%1,%2,%3};"         \
                 : "+f"((C)[0]), "+f"((C)[1]), "+f"((C)[2]), "+f"((C)[3])     \
                 : "r"((A)[0]), "r"((A)[1]), "r"((A)[2]), "r"((A)[3]),        \
                   "r"(B0), "r"(B1))

// ---------------------------------------------------------------------------
// prep: Whi/Wlo from ALPHA*g*wrec; init hist[0], hh[0], hl[0]
// ---------------------------------------------------------------------------
__global__ void prep_kernel(const float* __restrict__ wrec,
                            const float* __restrict__ g,
                            const float* __restrict__ h0) {
    int j = blockIdx.x;
    for (int k = threadIdx.x; k < Hdim; k += blockDim.x) {
        float w = ALPHA * g[k] * wrec[(size_t)j * Hdim + k];
        __nv_bfloat16 wh = __float2bfloat16_rn(w);
        g_Whi[(size_t)j * Hdim + k] = wh;
        g_Wlo[(size_t)j * Hdim + k] = __float2bfloat16_rn(w - __bfloat162float(wh));
    }
    if (j < Bdim) {
        for (int k = threadIdx.x; k < Hdim; k += blockDim.x) {
            float h = h0[k];
            g_hist[(size_t)j * Hdim + k] = h;
            __nv_bfloat16 hh = __float2bfloat16_rn(h);
            g_hh[0][(size_t)j * Hdim + k] = hh;
            g_hl[0][(size_t)j * Hdim + k] = __float2bfloat16_rn(h - __bfloat162float(hh));
        }
    }
    if (blockIdx.x == 0 && threadIdx.x < 16) g_cnt[threadIdx.x] = 0;
}

// ---------------------------------------------------------------------------
// xp: xp[t][b][j] = NSTD*noise[b][t][j] + ALPHA * sum_i x[b][t][i]*wi[i][j]
// ---------------------------------------------------------------------------
__global__ void xp_kernel(const float* __restrict__ x,
                          const float* __restrict__ noise,
                          const float* __restrict__ wi) {
    __shared__ float sx[64][68];
    __shared__ float sw[64][68];
    int t  = blockIdx.y;
    int c0 = blockIdx.x * 64;
    int tid = threadIdx.x;
    int tx = tid & 15, ty = tid >> 4;

    u64 acc[4][4];
    #pragma unroll
    for (int i = 0; i < 4; i++)
        #pragma unroll
        for (int j = 0; j < 4; j++) acc[i][j] = 0ull;

    for (int k0 = 0; k0 < Idim; k0 += 64) {
        #pragma unroll
        for (int i = 0; i < 4; i++) {
            int idx = tid + 256 * i;
            int b = idx >> 4, q = idx & 15;
            float4 v = *(const float4*)(x + ((size_t)b * Sdim + t) * Idim + k0 + q * 4);
            *(float4*)&sx[b][q * 4] = v;
        }
        #pragma unroll
        for (int i = 0; i < 4; i++) {
            int idx = tid + 256 * i;
            int kr = idx >> 4, q = idx & 15;
            float4 v = *(const float4*)(wi + ((size_t)(k0 + kr)) * Hdim + c0 + q * 4);
            sw[q * 4 + 0][kr] = v.x;
            sw[q * 4 + 1][kr] = v.y;
            sw[q * 4 + 2][kr] = v.z;
            sw[q * 4 + 3][kr] = v.w;
        }
        __syncthreads();
        #pragma unroll
        for (int kb = 0; kb < 64; kb += 2) {
            u64 ha[4], wb[4];
            #pragma unroll
            for (int i = 0; i < 4; i++) ha[i] = *(const u64*)&sx[ty + 16 * i][kb];
            #pragma unroll
            for (int j = 0; j < 4; j++) wb[j] = *(const u64*)&sw[tx + 16 * j][kb];
            #pragma unroll
            for (int i = 0; i < 4; i++)
                #pragma unroll
                for (int j = 0; j < 4; j++)
                    acc[i][j] = ffma2(ha[i], wb[j], acc[i][j]);
        }
        __syncthreads();
    }

    #pragma unroll
    for (int i = 0; i < 4; i++) {
        int b = ty + 16 * i;
        #pragma unroll
        for (int j = 0; j < 4; j++) {
            int jc = c0 + tx + 16 * j;
            float s = hsum2(acc[i][j]);
            float n = noise[((size_t)b * Sdim + t) * Hdim + jc];
            g_xp[((size_t)t * Bdim + b) * Hdim + jc] = NSTD * n + ALPHA * s;
        }
    }
}

// ---------------------------------------------------------------------------
// mma_step: partial[ks][b][j] = sum_{k in split} h[b][k]*W[j][k]  (bf16 3-product)
// grid (16 j-tiles, 8 k-splits), 256 threads. CTA: 64b x 128j x K=256.
// ks==0 CTA folds the seed (0.8*h + xp) into its partial. The LAST CTA to
// finish per j-tile (arrival counter) sums the 8 partials and writes
// h_{t+1} fp32 + bf16 hi/lo. One kernel per step -> small graph.
// ---------------------------------------------------------------------------
#define STG_BF 27648                     // bf16 per stage
#define OFF_HH 0
#define OFF_HL 4608
#define OFF_WH 9216
#define OFF_WL 18432
#define SMEM_MMA (4 * STG_BF * 2)        // 221184 bytes

extern __shared__ __nv_bfloat16 SB[];

__device__ __forceinline__ void mma_stage(const __nv_bfloat16* st,
                                          int b0, int j0w, int lane,
                                          float acc[2][4][4]) {
    const __nv_bfloat16* sh_hh = st + OFF_HH;
    const __nv_bfloat16* sh_hl = st + OFF_HL;
    const __nv_bfloat16* sh_wh = st + OFF_WH;
    const __nv_bfloat16* sh_wl = st + OFF_WL;
    int arow = (lane & 15), acol = (lane >> 4) << 3;
    int brow = ((lane >> 4) << 3) + (lane & 7), bcol = ((lane >> 3) & 1) << 3;

    #pragma unroll
    for (int kk = 0; kk < 64; kk += 16) {
        u32 ahi[2][4], alo[2][4], bhi[2][4], blo[2][4];
        #pragma unroll
        for (int mi = 0; mi < 2; mi++) {
            int off = (b0 + mi * 16 + arow) * 72 + kk + acol;
            LDSM4(ahi[mi], s2u(sh_hh + off));
            LDSM4(alo[mi], s2u(sh_hl + off));
        }
        #pragma unroll
        for (int ni = 0; ni < 2; ni++) {
            int off = (j0w + ni * 16 + brow) * 72 + kk + bcol;
            LDSM4(bhi[ni], s2u(sh_wh + off));
            LDSM4(blo[ni], s2u(sh_wl + off));
        }
        #pragma unroll
        for (int mi = 0; mi < 2; mi++)
            #pragma unroll
            for (int n = 0; n < 4; n++) {
                u32 bh0 = bhi[n >> 1][(n & 1) * 2], bh1 = bhi[n >> 1][(n & 1) * 2 + 1];
                u32 bl0 = blo[n >> 1][(n & 1) * 2], bl1 = blo[n >> 1][(n & 1) * 2 + 1];
                MMA16816(acc[mi][n], ahi[mi], bh0, bh1);
                MMA16816(acc[mi][n], alo[mi], bh0, bh1);
                MMA16816(acc[mi][n], ahi[mi], bl0, bl1);
            }
    }
}

__global__ void __launch_bounds__(256, 1) mma_step(int t) {
    int tid = threadIdx.x;
    int lane = tid & 31, warp = tid >> 5;
    int wb = warp >> 2, wj = warp & 3;
    int jt = blockIdx.x, ks = blockIdx.y;
    int j0g = jt * 128;
    int k0g = ks * 256;

    const __nv_bfloat16* HH = g_hh[t & 1];
    const __nv_bfloat16* HL = g_hl[t & 1];
    u32 sb = s2u(SB);

    // issue all 4 stages
    #pragma unroll
    for (int s = 0; s < 4; s++) {
        int kst = k0g + s * 64;
        u32 base = sb + s * STG_BF * 2;
        #pragma unroll
        for (int r = 0; r < 4; r++) {
            int c = tid + r * 256;
            int row = c >> 3, col = (c & 7) * 8;
            size_t go = (size_t)(j0g + row) * Hdim + kst + col;
            u32 so = (u32)(row * 72 + col) * 2;
            cp16(base + OFF_WH * 2 + so, g_Whi + go);
            cp16(base + OFF_WL * 2 + so, g_Wlo + go);
        }
        #pragma unroll
        for (int r = 0; r < 2; r++) {
            int c = tid + r * 256;
            int row = c >> 3, col = (c & 7) * 8;
            size_t go = (size_t)row * Hdim + kst + col;
            u32 so = (u32)(row * 72 + col) * 2;
            cp16(base + OFF_HH * 2 + so, HH + go);
            cp16(base + OFF_HL * 2 + so, HL + go);
        }
        CPCOMMIT();
    }

    float acc[2][4][4];
    #pragma unroll
    for (int mi = 0; mi < 2; mi++)
        #pragma unroll
        for (int n = 0; n < 4; n++)
            #pragma unroll
            for (int q = 0; q < 4; q++) acc[mi][n][q] = 0.0f;

    int b0 = wb * 32, j0w = wj * 32;

    CPWAIT(3); __syncthreads(); mma_stage(SB + 0 * STG_BF, b0, j0w, lane, acc);
    CPWAIT(2); __syncthreads(); mma_stage(SB + 1 * STG_BF, b0, j0w, lane, acc);
    CPWAIT(1); __syncthreads(); mma_stage(SB + 2 * STG_BF, b0, j0w, lane, acc);
    CPWAIT(0); __syncthreads(); mma_stage(SB + 3 * STG_BF, b0, j0w, lane, acc);

    // ---- write partials (ks==0 folds in 0.8*h + xp seed) ----
    const float* hin = g_hist + (size_t)t * Bdim * Hdim;
    const float* xp  = g_xp + (size_t)t * Bdim * Hdim;
    float* P = g_part[ks];
    #pragma unroll
    for (int mi = 0; mi < 2; mi++) {
        int r = b0 + mi * 16 + (lane >> 2);
        #pragma unroll
        for (int n = 0; n < 4; n++) {
            int c = j0g + j0w + n * 8 + (lane & 3) * 2;
            size_t i0 = (size_t)r * Hdim + c;
            size_t i1 = (size_t)(r + 8) * Hdim + c;
            float2 v0 = {acc[mi][n][0], acc[mi][n][1]};
            float2 v1 = {acc[mi][n][2], acc[mi][n][3]};
            if (ks == 0) {
                v0.x += (1.0f - ALPHA) * hin[i0]     + xp[i0];
                v0.y += (1.0f - ALPHA) * hin[i0 + 1] + xp[i0 + 1];
                v1.x += (1.0f - ALPHA) * hin[i1]     + xp[i1];
                v1.y += (1.0f - ALPHA) * hin[i1 + 1] + xp[i1 + 1];
            }
            *(float2*)&P[i0] = v0;
            *(float2*)&P[i1] = v1;
        }
    }

    // ---- last-arriving CTA of this j-tile does the fuse ----
    __threadfence();
    __syncthreads();
    __shared__ unsigned s_last;
    if (tid == 0) s_last = (atomicAdd(&g_cnt[jt], 1u) == 7u) ? 1u : 0u;
    __syncthreads();
    if (!s_last) return;
    __threadfence();

    float* hout = g_hist + (size_t)(t + 1) * Bdim * Hdim;
    u32* HHo = (u32*)g_hh[(t + 1) & 1];
    u32* HLo = (u32*)g_hl[(t + 1) & 1];

    #pragma unroll 2
    for (int it = tid; it < 2048; it += 256) {      // 64 rows x 32 float4
        int b = it >> 5, q = (it & 31) * 4;
        size_t off = (size_t)b * Hdim + j0g + q;
        float4 s = *(const float4*)&g_part[0][off];
        #pragma unroll
        for (int p = 1; p < 8; p++) {
            float4 v = *(const float4*)&g_part[p][off];
            s.x += v.x; s.y += v.y; s.z += v.z; s.w += v.w;
        }
        *(float4*)&hout[off] = s;

        __nv_bfloat16 hx = __float2bfloat16_rn(s.x);
        __nv_bfloat16 hy = __float2bfloat16_rn(s.y);
        __nv_bfloat16 hz = __float2bfloat16_rn(s.z);
        __nv_bfloat16 hw = __float2bfloat16_rn(s.w);
        union { __nv_bfloat16 h[2]; u32 u; } p0, p1, l0, l1;
        p0.h[0] = hx; p0.h[1] = hy;
        p1.h[0] = hz; p1.h[1] = hw;
        l0.h[0] = __float2bfloat16_rn(s.x - __bfloat162float(hx));
        l0.h[1] = __float2bfloat16_rn(s.y - __bfloat162float(hy));
        l1.h[0] = __float2bfloat16_rn(s.z - __bfloat162float(hz));
        l1.h[1] = __float2bfloat16_rn(s.w - __bfloat162float(hw));
        size_t o2 = off >> 1;
        HHo[o2] = p0.u; HHo[o2 + 1] = p1.u;
        HLo[o2] = l0.u; HLo[o2 + 1] = l1.u;
    }

    __syncthreads();
    if (tid == 0) g_cnt[jt] = 0;    // reset for next launch / replay
}

// ---------------------------------------------------------------------------
// out: out[b][t][o] = sum_k hist[t][b][k] * wout[k][o]
// ---------------------------------------------------------------------------
__global__ void out_kernel(const float* __restrict__ wout,
                           float* __restrict__ out) {
    __shared__ float sh[64][68];
    __shared__ float sw[64][68];
    int t  = blockIdx.y;
    int c0 = blockIdx.x * 64;
    int tid = threadIdx.x;
    int tx = tid & 15, ty = tid >> 4;

    u64 acc[4][4];
    #pragma unroll
    for (int i = 0; i < 4; i++)
        #pragma unroll
        for (int j = 0; j < 4; j++) acc[i][j] = 0ull;

    const float* hin = g_hist + (size_t)t * Bdim * Hdim;

    for (int k0 = 0; k0 < Hdim; k0 += 64) {
        #pragma unroll
        for (int i = 0; i < 4; i++) {
            int idx = tid + 256 * i;
            int b = idx >> 4, q = idx & 15;
            *(float4*)&sh[b][q * 4] = *(const float4*)(hin + (size_t)b * Hdim + k0 + q * 4);
        }
        #pragma unroll
        for (int i = 0; i < 4; i++) {
            int idx = tid + 256 * i;
            int kr = idx >> 4, q = idx & 15;
            float4 v = *(const float4*)(wout + ((size_t)(k0 + kr)) * Odim + c0 + q * 4);
            sw[q * 4 + 0][kr] = v.x;
            sw[q * 4 + 1][kr] = v.y;
            sw[q * 4 + 2][kr] = v.z;
            sw[q * 4 + 3][kr] = v.w;
        }
        __syncthreads();
        #pragma unroll
        for (int kb = 0; kb < 64; kb += 2) {
            u64 ha[4], wb[4];
            #pragma unroll
            for (int i = 0; i < 4; i++) ha[i] = *(const u64*)&sh[ty + 16 * i][kb];
            #pragma unroll
            for (int j = 0; j < 4; j++) wb[j] = *(const u64*)&sw[tx + 16 * j][kb];
            #pragma unroll
            for (int i = 0; i < 4; i++)
                #pragma unroll
                for (int j = 0; j < 4; j++)
                    acc[i][j] = ffma2(ha[i], wb[j], acc[i][j]);
        }
        __syncthreads();
    }

    #pragma unroll
    for (int i = 0; i < 4; i++) {
        int b = ty + 16 * i;
        #pragma unroll
        for (int j = 0; j < 4; j++) {
            int o = c0 + tx + 16 * j;
            out[((size_t)b * Sdim + t) * Odim + o] = hsum2(acc[i][j]);
        }
    }
}

// ---------------------------------------------------------------------------
extern "C" void kernel_launch(void* const* d_in, const int* in_sizes, int n_in,
                              void* d_out, int out_size) {
    const float* x     = (const float*)d_in[0];
    const float* noise = (const float*)d_in[1];
    const float* wi    = (const float*)d_in[2];
    const float* wrec  = (const float*)d_in[3];
    const float* wout  = (const float*)d_in[4];
    const float* g     = (const float*)d_in[5];
    const float* h0    = (const float*)d_in[6];
    float* out = (float*)d_out;

    cudaFuncSetAttribute(mma_step, cudaFuncAttributeMaxDynamicSharedMemorySize,
                         SMEM_MMA);

    prep_kernel<<<Hdim, 256>>>(wrec, g, h0);
    xp_kernel<<<dim3(Hdim / 64, Sdim - 1), 256>>>(x, noise, wi);
    for (int t = 0; t < Sdim - 1; t++)
        mma_step<<<dim3(16, 8), 256, SMEM_MMA>>>(t);
    out_kernel<<<dim3(Odim / 64, Sdim), 256>>>(wout, out);
}

// round 12
// speedup vs baseline: 2.8103x; 1.1373x over previous
#include <cuda_runtime.h>
#include <cuda.h>
#include <cuda_bf16.h>
#include <cstdint>
#include <cstddef>

#define Bdim 64
#define Sdim 512
#define Idim 128
#define Hdim 2048
#define Odim 128
#define ALPHA 0.2f
#define NSTD  0.005f

// ---- device scratch ----
__device__ __align__(1024) __nv_bfloat16 g_Whi[(size_t)Hdim * Hdim];
__device__ __align__(1024) __nv_bfloat16 g_Wlo[(size_t)Hdim * Hdim];
__device__ __align__(1024) __nv_bfloat16 g_hh[2][(size_t)Bdim * Hdim];
__device__ __align__(1024) __nv_bfloat16 g_hl[2][(size_t)Bdim * Hdim];
__device__ float g_hist[(size_t)Sdim * Bdim * Hdim];      // h_t fp32, [t][b][k]
__device__ float g_xp[(size_t)(Sdim - 1) * Bdim * Hdim];  // NSTD*noise + ALPHA*x@wi
__device__ float g_part[8][(size_t)Bdim * Hdim];          // k-split partials
__device__ unsigned g_cnt[16];                            // per-j-tile arrival counters

typedef unsigned long long u64;
typedef unsigned int u32;

__device__ __forceinline__ u64 ffma2(u64 a, u64 b, u64 c) {
    u64 d;
    asm("fma.rn.f32x2 %0, %1, %2, %3;" : "=l"(d) : "l"(a), "l"(b), "l"(c));
    return d;
}
__device__ __forceinline__ float hsum2(u64 a) {
    float2 f = *reinterpret_cast<float2*>(&a);
    return f.x + f.y;
}
__device__ __forceinline__ u32 s2u(const void* p) {
    return (u32)__cvta_generic_to_shared(p);
}
__device__ __forceinline__ u32 swz(u32 off) {           // SW128 swizzle
    return off ^ ((off >> 3) & 0x70);
}

#define LDSM4(R, ADDR)                                                        \
    asm volatile("ldmatrix.sync.aligned.m8n8.x4.shared.b16 {%0,%1,%2,%3},[%4];" \
                 : "=r"((R)[0]), "=r"((R)[1]), "=r"((R)[2]), "=r"((R)[3])     \
                 : "r"(ADDR))

#define MMA16816(C, A, B0, B1)                                                \
    asm volatile("mma.sync.aligned.m16n8k16.row.col.f32.bf16.bf16.f32 "       \
                 "{%0,%1,%2,%3},{%4,%5,%6,%7},{%8,%9},{%0,%1,%2,%3};"         \
                 : "+f"((C)[0]), "+f"((C)[1]), "+f"((C)[2]), "+f"((C)[3])     \
                 : "r"((A)[0]), "r"((A)[1]), "r"((A)[2]), "r"((A)[3]),        \
                   "r"(B0), "r"(B1))

#define MBAR_INIT(A, N) \
    asm volatile("mbarrier.init.shared.b64 [%0], %1;" :: "r"(A), "r"(N) : "memory")
#define MBAR_EXPECT(A, B) \
    asm volatile("mbarrier.arrive.expect_tx.shared.b64 _, [%0], %1;" :: "r"(A), "r"(B) : "memory")
#define MBAR_WAIT(A, PH) do {                                                 \
    asm volatile(                                                             \
        "{\n\t.reg .pred P1;\n\t"                                             \
        "WAIT_LOOP_%=:\n\t"                                                   \
        "mbarrier.try_wait.parity.acquire.cta.shared::cta.b64 P1, [%0], %1, 0x989680;\n\t" \
        "@P1 bra.uni WAIT_DONE_%=;\n\t"                                       \
        "bra.uni WAIT_LOOP_%=;\n\t"                                           \
        "WAIT_DONE_%=:\n\t}"                                                  \
        :: "r"(A), "r"(PH) : "memory");                                       \
} while (0)

#define TMA2D(SMEM, MAP, X, Y, MB)                                            \
    asm volatile("cp.async.bulk.tensor.2d.shared::cta.global.tile"            \
                 ".mbarrier::complete_tx::bytes [%0], [%1, {%2, %3}], [%4];"  \
                 :: "r"(SMEM), "l"(MAP), "r"(X), "r"(Y), "r"(MB) : "memory")

// ---------------------------------------------------------------------------
// prep: Whi/Wlo from ALPHA*g*wrec; init hist[0], hh[0], hl[0]
// ---------------------------------------------------------------------------
__global__ void prep_kernel(const float* __restrict__ wrec,
                            const float* __restrict__ g,
                            const float* __restrict__ h0) {
    int j = blockIdx.x;
    for (int k = threadIdx.x; k < Hdim; k += blockDim.x) {
        float w = ALPHA * g[k] * wrec[(size_t)j * Hdim + k];
        __nv_bfloat16 wh = __float2bfloat16_rn(w);
        g_Whi[(size_t)j * Hdim + k] = wh;
        g_Wlo[(size_t)j * Hdim + k] = __float2bfloat16_rn(w - __bfloat162float(wh));
    }
    if (j < Bdim) {
        for (int k = threadIdx.x; k < Hdim; k += blockDim.x) {
            float h = h0[k];
            g_hist[(size_t)j * Hdim + k] = h;
            __nv_bfloat16 hh = __float2bfloat16_rn(h);
            g_hh[0][(size_t)j * Hdim + k] = hh;
            g_hl[0][(size_t)j * Hdim + k] = __float2bfloat16_rn(h - __bfloat162float(hh));
        }
    }
    if (blockIdx.x == 0 && threadIdx.x < 16) g_cnt[threadIdx.x] = 0;
}

// ---------------------------------------------------------------------------
// xp: xp[t][b][j] = NSTD*noise[b][t][j] + ALPHA * sum_i x[b][t][i]*wi[i][j]
// ---------------------------------------------------------------------------
__global__ void xp_kernel(const float* __restrict__ x,
                          const float* __restrict__ noise,
                          const float* __restrict__ wi) {
    __shared__ float sx[64][68];
    __shared__ float sw[64][68];
    int t  = blockIdx.y;
    int c0 = blockIdx.x * 64;
    int tid = threadIdx.x;
    int tx = tid & 15, ty = tid >> 4;

    u64 acc[4][4];
    #pragma unroll
    for (int i = 0; i < 4; i++)
        #pragma unroll
        for (int j = 0; j < 4; j++) acc[i][j] = 0ull;

    for (int k0 = 0; k0 < Idim; k0 += 64) {
        #pragma unroll
        for (int i = 0; i < 4; i++) {
            int idx = tid + 256 * i;
            int b = idx >> 4, q = idx & 15;
            float4 v = *(const float4*)(x + ((size_t)b * Sdim + t) * Idim + k0 + q * 4);
            *(float4*)&sx[b][q * 4] = v;
        }
        #pragma unroll
        for (int i = 0; i < 4; i++) {
            int idx = tid + 256 * i;
            int kr = idx >> 4, q = idx & 15;
            float4 v = *(const float4*)(wi + ((size_t)(k0 + kr)) * Hdim + c0 + q * 4);
            sw[q * 4 + 0][kr] = v.x;
            sw[q * 4 + 1][kr] = v.y;
            sw[q * 4 + 2][kr] = v.z;
            sw[q * 4 + 3][kr] = v.w;
        }
        __syncthreads();
        #pragma unroll
        for (int kb = 0; kb < 64; kb += 2) {
            u64 ha[4], wb[4];
            #pragma unroll
            for (int i = 0; i < 4; i++) ha[i] = *(const u64*)&sx[ty + 16 * i][kb];
            #pragma unroll
            for (int j = 0; j < 4; j++) wb[j] = *(const u64*)&sw[tx + 16 * j][kb];
            #pragma unroll
            for (int i = 0; i < 4; i++)
                #pragma unroll
                for (int j = 0; j < 4; j++)
                    acc[i][j] = ffma2(ha[i], wb[j], acc[i][j]);
        }
        __syncthreads();
    }

    #pragma unroll
    for (int i = 0; i < 4; i++) {
        int b = ty + 16 * i;
        #pragma unroll
        for (int j = 0; j < 4; j++) {
            int jc = c0 + tx + 16 * j;
            float s = hsum2(acc[i][j]);
            float n = noise[((size_t)b * Sdim + t) * Hdim + jc];
            g_xp[((size_t)t * Bdim + b) * Hdim + jc] = NSTD * n + ALPHA * s;
        }
    }
}

// ---------------------------------------------------------------------------
// mma_step (TMA version)
// grid (16 j-tiles, 8 k-splits), 256 threads. CTA: 64b x 128j x K=256.
// 4 stages of k=64, each 48KB, loaded by TMA (SW128) into dyn smem.
// ks==0 CTA folds the seed; last CTA per j-tile fuses partials.
// ---------------------------------------------------------------------------
#define OFF_HH 0
#define OFF_HL 8192
#define OFF_WH 16384
#define OFF_WL 32768
#define STG_BYTES 49152
#define SMEM_MMA (4 * STG_BYTES + 1024)

extern __shared__ __align__(1024) char SBraw[];

__device__ __forceinline__ void mma_stage(u32 st, int b0, int j0w, int lane,
                                          float acc[2][4][4]) {
    u32 hh = st + OFF_HH, hl = st + OFF_HL;
    u32 wh = st + OFF_WH, wl = st + OFF_WL;
    int arow = (lane & 15);
    u32 acb = (u32)(lane >> 4) * 16;                 // A granule byte offset
    int brow = ((lane >> 4) << 3) + (lane & 7);
    u32 bcb = (u32)((lane >> 3) & 1) * 16;           // B granule byte offset

    #pragma unroll
    for (int kk = 0; kk < 64; kk += 16) {
        u32 ahi[2][4], alo[2][4], bhi[2][4], blo[2][4];
        #pragma unroll
        for (int mi = 0; mi < 2; mi++) {
            u32 off = swz((u32)(b0 + mi * 16 + arow) * 128 + acb + kk * 2);
            LDSM4(ahi[mi], hh + off);
            LDSM4(alo[mi], hl + off);
        }
        #pragma unroll
        for (int ni = 0; ni < 2; ni++) {
            u32 off = swz((u32)(j0w + ni * 16 + brow) * 128 + bcb + kk * 2);
            LDSM4(bhi[ni], wh + off);
            LDSM4(blo[ni], wl + off);
        }
        #pragma unroll
        for (int mi = 0; mi < 2; mi++)
            #pragma unroll
            for (int n = 0; n < 4; n++) {
                u32 bh0 = bhi[n >> 1][(n & 1) * 2], bh1 = bhi[n >> 1][(n & 1) * 2 + 1];
                u32 bl0 = blo[n >> 1][(n & 1) * 2], bl1 = blo[n >> 1][(n & 1) * 2 + 1];
                MMA16816(acc[mi][n], ahi[mi], bh0, bh1);
                MMA16816(acc[mi][n], alo[mi], bh0, bh1);
                MMA16816(acc[mi][n], ahi[mi], bl0, bl1);
            }
    }
}

__global__ void __launch_bounds__(256, 1) mma_step(
    int t,
    const __grid_constant__ CUtensorMap mWh,
    const __grid_constant__ CUtensorMap mWl,
    const __grid_constant__ CUtensorMap mH0,
    const __grid_constant__ CUtensorMap mH1,
    const __grid_constant__ CUtensorMap mL0,
    const __grid_constant__ CUtensorMap mL1) {
    int tid = threadIdx.x;
    int lane = tid & 31, warp = tid >> 5;
    int wb = warp >> 2, wj = warp & 3;
    int jt = blockIdx.x, ks = blockIdx.y;
    int j0g = jt * 128;
    int k0g = ks * 256;

    __shared__ __align__(8) u64 mbar[4];
    u32 sbase = (s2u(SBraw) + 1023) & ~1023u;

    if (tid == 0) {
        #pragma unroll
        for (int s = 0; s < 4; s++) MBAR_INIT(s2u(&mbar[s]), 1);
    }
    __syncthreads();

    const CUtensorMap* pH = (t & 1) ? &mH1 : &mH0;
    const CUtensorMap* pL = (t & 1) ? &mL1 : &mL0;

    if (tid == 0) {
        #pragma unroll
        for (int s = 0; s < 4; s++) {
            int kx = k0g + s * 64;
            u32 st = sbase + s * STG_BYTES;
            u32 mb = s2u(&mbar[s]);
            MBAR_EXPECT(mb, STG_BYTES);
            TMA2D(st + OFF_HH, pH, kx, 0, mb);
            TMA2D(st + OFF_HL, pL, kx, 0, mb);
            TMA2D(st + OFF_WH, &mWh, kx, j0g, mb);
            TMA2D(st + OFF_WL, &mWl, kx, j0g, mb);
        }
    }

    float acc[2][4][4];
    #pragma unroll
    for (int mi = 0; mi < 2; mi++)
        #pragma unroll
        for (int n = 0; n < 4; n++)
            #pragma unroll
            for (int q = 0; q < 4; q++) acc[mi][n][q] = 0.0f;

    int b0 = wb * 32, j0w = wj * 32;

    #pragma unroll
    for (int s = 0; s < 4; s++) {
        MBAR_WAIT(s2u(&mbar[s]), 0);
        mma_stage(sbase + s * STG_BYTES, b0, j0w, lane, acc);
    }

    // ---- write partials (ks==0 folds in 0.8*h + xp seed) ----
    const float* hin = g_hist + (size_t)t * Bdim * Hdim;
    const float* xp  = g_xp + (size_t)t * Bdim * Hdim;
    float* P = g_part[ks];
    #pragma unroll
    for (int mi = 0; mi < 2; mi++) {
        int r = b0 + mi * 16 + (lane >> 2);
        #pragma unroll
        for (int n = 0; n < 4; n++) {
            int c = j0g + j0w + n * 8 + (lane & 3) * 2;
            size_t i0 = (size_t)r * Hdim + c;
            size_t i1 = (size_t)(r + 8) * Hdim + c;
            float2 v0 = {acc[mi][n][0], acc[mi][n][1]};
            float2 v1 = {acc[mi][n][2], acc[mi][n][3]};
            if (ks == 0) {
                v0.x += (1.0f - ALPHA) * hin[i0]     + xp[i0];
                v0.y += (1.0f - ALPHA) * hin[i0 + 1] + xp[i0 + 1];
                v1.x += (1.0f - ALPHA) * hin[i1]     + xp[i1];
                v1.y += (1.0f - ALPHA) * hin[i1 + 1] + xp[i1 + 1];
            }
            *(float2*)&P[i0] = v0;
            *(float2*)&P[i1] = v1;
        }
    }

    // ---- last-arriving CTA of this j-tile does the fuse ----
    __threadfence();
    __syncthreads();
    __shared__ unsigned s_last;
    if (tid == 0) s_last = (atomicAdd(&g_cnt[jt], 1u) == 7u) ? 1u : 0u;
    __syncthreads();
    if (!s_last) return;
    __threadfence();

    float* hout = g_hist + (size_t)(t + 1) * Bdim * Hdim;
    u32* HHo = (u32*)g_hh[(t + 1) & 1];
    u32* HLo = (u32*)g_hl[(t + 1) & 1];

    #pragma unroll 2
    for (int it = tid; it < 2048; it += 256) {      // 64 rows x 32 float4
        int b = it >> 5, q = (it & 31) * 4;
        size_t off = (size_t)b * Hdim + j0g + q;
        float4 s = *(const float4*)&g_part[0][off];
        #pragma unroll
        for (int p = 1; p < 8; p++) {
            float4 v = *(const float4*)&g_part[p][off];
            s.x += v.x; s.y += v.y; s.z += v.z; s.w += v.w;
        }
        *(float4*)&hout[off] = s;

        __nv_bfloat16 hx = __float2bfloat16_rn(s.x);
        __nv_bfloat16 hy = __float2bfloat16_rn(s.y);
        __nv_bfloat16 hz = __float2bfloat16_rn(s.z);
        __nv_bfloat16 hw = __float2bfloat16_rn(s.w);
        union { __nv_bfloat16 h[2]; u32 u; } p0, p1, l0, l1;
        p0.h[0] = hx; p0.h[1] = hy;
        p1.h[0] = hz; p1.h[1] = hw;
        l0.h[0] = __float2bfloat16_rn(s.x - __bfloat162float(hx));
        l0.h[1] = __float2bfloat16_rn(s.y - __bfloat162float(hy));
        l1.h[0] = __float2bfloat16_rn(s.z - __bfloat162float(hz));
        l1.h[1] = __float2bfloat16_rn(s.w - __bfloat162float(hw));
        size_t o2 = off >> 1;
        HHo[o2] = p0.u; HHo[o2 + 1] = p1.u;
        HLo[o2] = l0.u; HLo[o2 + 1] = l1.u;
    }

    __syncthreads();
    if (tid == 0) g_cnt[jt] = 0;    // reset for next launch / replay
}

// ---------------------------------------------------------------------------
// out: out[b][t][o] = sum_k hist[t][b][k] * wout[k][o]
// ---------------------------------------------------------------------------
__global__ void out_kernel(const float* __restrict__ wout,
                           float* __restrict__ out) {
    __shared__ float sh[64][68];
    __shared__ float sw[64][68];
    int t  = blockIdx.y;
    int c0 = blockIdx.x * 64;
    int tid = threadIdx.x;
    int tx = tid & 15, ty = tid >> 4;

    u64 acc[4][4];
    #pragma unroll
    for (int i = 0; i < 4; i++)
        #pragma unroll
        for (int j = 0; j < 4; j++) acc[i][j] = 0ull;

    const float* hin = g_hist + (size_t)t * Bdim * Hdim;

    for (int k0 = 0; k0 < Hdim; k0 += 64) {
        #pragma unroll
        for (int i = 0; i < 4; i++) {
            int idx = tid + 256 * i;
            int b = idx >> 4, q = idx & 15;
            *(float4*)&sh[b][q * 4] = *(const float4*)(hin + (size_t)b * Hdim + k0 + q * 4);
        }
        #pragma unroll
        for (int i = 0; i < 4; i++) {
            int idx = tid + 256 * i;
            int kr = idx >> 4, q = idx & 15;
            float4 v = *(const float4*)(wout + ((size_t)(k0 + kr)) * Odim + c0 + q * 4);
            sw[q * 4 + 0][kr] = v.x;
            sw[q * 4 + 1][kr] = v.y;
            sw[q * 4 + 2][kr] = v.z;
            sw[q * 4 + 3][kr] = v.w;
        }
        __syncthreads();
        #pragma unroll
        for (int kb = 0; kb < 64; kb += 2) {
            u64 ha[4], wb[4];
            #pragma unroll
            for (int i = 0; i < 4; i++) ha[i] = *(const u64*)&sh[ty + 16 * i][kb];
            #pragma unroll
            for (int j = 0; j < 4; j++) wb[j] = *(const u64*)&sw[tx + 16 * j][kb];
            #pragma unroll
            for (int i = 0; i < 4; i++)
                #pragma unroll
                for (int j = 0; j < 4; j++)
                    acc[i][j] = ffma2(ha[i], wb[j], acc[i][j]);
        }
        __syncthreads();
    }

    #pragma unroll
    for (int i = 0; i < 4; i++) {
        int b = ty + 16 * i;
        #pragma unroll
        for (int j = 0; j < 4; j++) {
            int o = c0 + tx + 16 * j;
            out[((size_t)b * Sdim + t) * Odim + o] = hsum2(acc[i][j]);
        }
    }
}

// ---------------------------------------------------------------------------
// host: tensormap construction via driver entry point (no -lcuda needed)
// ---------------------------------------------------------------------------
typedef CUresult (*PFN_TMEnc)(CUtensorMap*, CUtensorMapDataType, cuuint32_t,
                              void*, const cuuint64_t*, const cuuint64_t*,
                              const cuuint32_t*, const cuuint32_t*,
                              CUtensorMapInterleave, CUtensorMapSwizzle,
                              CUtensorMapL2promotion, CUtensorMapFloatOOBfill);

static void make_map(PFN_TMEnc enc, CUtensorMap* m, void* base,
                     cuuint64_t d0, cuuint64_t d1, cuuint32_t b0, cuuint32_t b1) {
    cuuint64_t dims[2] = {d0, d1};
    cuuint64_t strides[1] = {d0 * 2};
    cuuint32_t box[2] = {b0, b1};
    cuuint32_t es[2] = {1, 1};
    enc(m, CU_TENSOR_MAP_DATA_TYPE_BFLOAT16, 2, base, dims, strides, box, es,
        CU_TENSOR_MAP_INTERLEAVE_NONE, CU_TENSOR_MAP_SWIZZLE_128B,
        CU_TENSOR_MAP_L2_PROMOTION_L2_128B, CU_TENSOR_MAP_FLOAT_OOB_FILL_NONE);
}

extern "C" void kernel_launch(void* const* d_in, const int* in_sizes, int n_in,
                              void* d_out, int out_size) {
    const float* x     = (const float*)d_in[0];
    const float* noise = (const float*)d_in[1];
    const float* wi    = (const float*)d_in[2];
    const float* wrec  = (const float*)d_in[3];
    const float* wout  = (const float*)d_in[4];
    const float* g     = (const float*)d_in[5];
    const float* h0    = (const float*)d_in[6];
    float* out = (float*)d_out;

    // driver entry point for cuTensorMapEncodeTiled
    PFN_TMEnc enc = nullptr;
    {
        void* fn = nullptr;
        cudaDriverEntryPointQueryResult qr;
        cudaGetDriverEntryPoint("cuTensorMapEncodeTiled", &fn,
                                cudaEnableDefault, &qr);
        enc = (PFN_TMEnc)fn;
    }

    void *pWh, *pWl, *pHH, *pHL;
    cudaGetSymbolAddress(&pWh, g_Whi);
    cudaGetSymbolAddress(&pWl, g_Wlo);
    cudaGetSymbolAddress(&pHH, g_hh);
    cudaGetSymbolAddress(&pHL, g_hl);
    size_t hbytes = (size_t)Bdim * Hdim * 2;

    CUtensorMap mWh, mWl, mH0, mH1, mL0, mL1;
    make_map(enc, &mWh, pWh, Hdim, Hdim, 64, 128);
    make_map(enc, &mWl, pWl, Hdim, Hdim, 64, 128);
    make_map(enc, &mH0, pHH, Hdim, Bdim, 64, 64);
    make_map(enc, &mH1, (char*)pHH + hbytes, Hdim, Bdim, 64, 64);
    make_map(enc, &mL0, pHL, Hdim, Bdim, 64, 64);
    make_map(enc, &mL1, (char*)pHL + hbytes, Hdim, Bdim, 64, 64);

    cudaFuncSetAttribute(mma_step, cudaFuncAttributeMaxDynamicSharedMemorySize,
                         SMEM_MMA);

    prep_kernel<<<Hdim, 256>>>(wrec, g, h0);
    xp_kernel<<<dim3(Hdim / 64, Sdim - 1), 256>>>(x, noise, wi);
    for (int t = 0; t < Sdim - 1; t++)
        mma_step<<<dim3(16, 8), 256, SMEM_MMA>>>(t, mWh, mWl, mH0, mH1, mL0, mL1);
    out_kernel<<<dim3(Odim / 64, Sdim), 256>>>(wout, out);
}

// round 14
// speedup vs baseline: 3.1150x; 1.1084x over previous
#include <cuda_runtime.h>
#include <cuda.h>
#include <cuda_bf16.h>
#include <cstdint>
#include <cstddef>

#define Bdim 64
#define Sdim 512
#define Idim 128
#define Hdim 2048
#define Odim 128
#define ALPHA 0.2f
#define NSTD  0.005f

// ---- device scratch ----
__device__ __align__(1024) __nv_bfloat16 g_Whi[(size_t)Hdim * Hdim];
__device__ __align__(1024) __nv_bfloat16 g_Wlo[(size_t)Hdim * Hdim];
__device__ __align__(1024) __nv_bfloat16 g_hh[2][(size_t)Bdim * Hdim];
__device__ __align__(1024) __nv_bfloat16 g_hl[2][(size_t)Bdim * Hdim];
__device__ float g_hist[(size_t)Sdim * Bdim * Hdim];      // h_t fp32, [t][b][k]
__device__ float g_xp[(size_t)(Sdim - 1) * Bdim * Hdim];  // NSTD*noise + ALPHA*x@wi
__device__ float g_part[2][(size_t)Bdim * Hdim];          // k-split partials
__device__ unsigned g_cnt[64];                            // per-j-tile arrival counters

typedef unsigned long long u64;
typedef unsigned int u32;

__device__ __forceinline__ u64 ffma2(u64 a, u64 b, u64 c) {
    u64 d;
    asm("fma.rn.f32x2 %0, %1, %2, %3;" : "=l"(d) : "l"(a), "l"(b), "l"(c));
    return d;
}
__device__ __forceinline__ float hsum2(u64 a) {
    float2 f = *reinterpret_cast<float2*>(&a);
    return f.x + f.y;
}
__device__ __forceinline__ u32 s2u(const void* p) {
    return (u32)__cvta_generic_to_shared(p);
}
__device__ __forceinline__ u32 swz(u32 off) {           // SW128 swizzle
    return off ^ ((off >> 3) & 0x70);
}

#define LDSM4(R, ADDR)                                                        \
    asm volatile("ldmatrix.sync.aligned.m8n8.x4.shared.b16 {%0,%1,%2,%3},[%4];" \
                 : "=r"((R)[0]), "=r"((R)[1]), "=r"((R)[2]), "=r"((R)[3])     \
                 : "r"(ADDR))

#define MMA16816(C, A, B0, B1)                                                \
    asm volatile("mma.sync.aligned.m16n8k16.row.col.f32.bf16.bf16.f32 "       \
                 "{%0,%1,%2,%3},{%4,%5,%6,%7},{%8,%9},{%0,%1,%2,%3};"         \
                 : "+f"((C)[0]), "+f"((C)[1]), "+f"((C)[2]), "+f"((C)[3])     \
                 : "r"((A)[0]), "r"((A)[1]), "r"((A)[2]), "r"((A)[3]),        \
                   "r"(B0), "r"(B1))

#define MBAR_INIT(A, N) \
    asm volatile("mbarrier.init.shared.b64 [%0], %1;" :: "r"(A), "r"(N) : "memory")
#define MBAR_EXPECT(A, B) \
    asm volatile("mbarrier.arrive.expect_tx.shared.b64 _, [%0], %1;" :: "r"(A), "r"(B) : "memory")
#define MBAR_WAIT(A, PH) do {                                                 \
    asm volatile(                                                             \
        "{\n\t.reg .pred P1;\n\t"                                             \
        "WAIT_LOOP_%=:\n\t"                                                   \
        "mbarrier.try_wait.parity.acquire.cta.shared::cta.b64 P1, [%0], %1, 0x989680;\n\t" \
        "@P1 bra.uni WAIT_DONE_%=;\n\t"                                       \
        "bra.uni WAIT_LOOP_%=;\n\t"                                           \
        "WAIT_DONE_%=:\n\t}"                                                  \
        :: "r"(A), "r"(PH) : "memory");                                       \
} while (0)

#define TMA2D(SMEM, MAP, X, Y, MB)                                            \
    asm volatile("cp.async.bulk.tensor.2d.shared::cta.global.tile"            \
                 ".mbarrier::complete_tx::bytes [%0], [%1, {%2, %3}], [%4];"  \
                 :: "r"(SMEM), "l"(MAP), "r"(X), "r"(Y), "r"(MB) : "memory")

// ---------------------------------------------------------------------------
// prep: Whi/Wlo from ALPHA*g*wrec; init hist[0], hh[0], hl[0]
// ---------------------------------------------------------------------------
__global__ void prep_kernel(const float* __restrict__ wrec,
                            const float* __restrict__ g,
                            const float* __restrict__ h0) {
    int j = blockIdx.x;
    for (int k = threadIdx.x; k < Hdim; k += blockDim.x) {
        float w = ALPHA * g[k] * wrec[(size_t)j * Hdim + k];
        __nv_bfloat16 wh = __float2bfloat16_rn(w);
        g_Whi[(size_t)j * Hdim + k] = wh;
        g_Wlo[(size_t)j * Hdim + k] = __float2bfloat16_rn(w - __bfloat162float(wh));
    }
    if (j < Bdim) {
        for (int k = threadIdx.x; k < Hdim; k += blockDim.x) {
            float h = h0[k];
            g_hist[(size_t)j * Hdim + k] = h;
            __nv_bfloat16 hh = __float2bfloat16_rn(h);
            g_hh[0][(size_t)j * Hdim + k] = hh;
            g_hl[0][(size_t)j * Hdim + k] = __float2bfloat16_rn(h - __bfloat162float(hh));
        }
    }
    if (blockIdx.x == 0 && threadIdx.x < 64) g_cnt[threadIdx.x] = 0;
}

// ---------------------------------------------------------------------------
// xp: xp[t][b][j] = NSTD*noise[b][t][j] + ALPHA * sum_i x[b][t][i]*wi[i][j]
// ---------------------------------------------------------------------------
__global__ void xp_kernel(const float* __restrict__ x,
                          const float* __restrict__ noise,
                          const float* __restrict__ wi) {
    __shared__ float sx[64][68];
    __shared__ float sw[64][68];
    int t  = blockIdx.y;
    int c0 = blockIdx.x * 64;
    int tid = threadIdx.x;
    int tx = tid & 15, ty = tid >> 4;

    u64 acc[4][4];
    #pragma unroll
    for (int i = 0; i < 4; i++)
        #pragma unroll
        for (int j = 0; j < 4; j++) acc[i][j] = 0ull;

    for (int k0 = 0; k0 < Idim; k0 += 64) {
        #pragma unroll
        for (int i = 0; i < 4; i++) {
            int idx = tid + 256 * i;
            int b = idx >> 4, q = idx & 15;
            float4 v = *(const float4*)(x + ((size_t)b * Sdim + t) * Idim + k0 + q * 4);
            *(float4*)&sx[b][q * 4] = v;
        }
        #pragma unroll
        for (int i = 0; i < 4; i++) {
            int idx = tid + 256 * i;
            int kr = idx >> 4, q = idx & 15;
            float4 v = *(const float4*)(wi + ((size_t)(k0 + kr)) * Hdim + c0 + q * 4);
            sw[q * 4 + 0][kr] = v.x;
            sw[q * 4 + 1][kr] = v.y;
            sw[q * 4 + 2][kr] = v.z;
            sw[q * 4 + 3][kr] = v.w;
        }
        __syncthreads();
        #pragma unroll
        for (int kb = 0; kb < 64; kb += 2) {
            u64 ha[4], wb[4];
            #pragma unroll
            for (int i = 0; i < 4; i++) ha[i] = *(const u64*)&sx[ty + 16 * i][kb];
            #pragma unroll
            for (int j = 0; j < 4; j++) wb[j] = *(const u64*)&sw[tx + 16 * j][kb];
            #pragma unroll
            for (int i = 0; i < 4; i++)
                #pragma unroll
                for (int j = 0; j < 4; j++)
                    acc[i][j] = ffma2(ha[i], wb[j], acc[i][j]);
        }
        __syncthreads();
    }

    #pragma unroll
    for (int i = 0; i < 4; i++) {
        int b = ty + 16 * i;
        #pragma unroll
        for (int j = 0; j < 4; j++) {
            int jc = c0 + tx + 16 * j;
            float s = hsum2(acc[i][j]);
            float n = noise[((size_t)b * Sdim + t) * Hdim + jc];
            g_xp[((size_t)t * Bdim + b) * Hdim + jc] = NSTD * n + ALPHA * s;
        }
    }
}

// ---------------------------------------------------------------------------
// mma_step: grid (64 j-tiles, 2 k-splits), 256 threads.
// CTA: 64b x 32j x K=1024. 8-deep TMA ring of k=64 stages (24KB each).
// Warp (8) = (b quarter 16) x (j half 16). acc stays in registers; the
// last-arriving CTA of the pair adds the peer's 8KB partial and writes
// h_{t+1} fp32 + bf16 hi/lo directly from registers.
// ---------------------------------------------------------------------------
#define S_HH 0
#define S_HL 8192
#define S_WH 16384
#define S_WL 20480
#define STG_BYTES 24576
#define NSTG 8
#define SMEM_MMA (NSTG * STG_BYTES + 1024)

extern __shared__ __align__(1024) char SBraw[];

__global__ void __launch_bounds__(256, 1) mma_step(
    int t,
    const __grid_constant__ CUtensorMap mWh,
    const __grid_constant__ CUtensorMap mWl,
    const __grid_constant__ CUtensorMap mH0,
    const __grid_constant__ CUtensorMap mH1,
    const __grid_constant__ CUtensorMap mL0,
    const __grid_constant__ CUtensorMap mL1) {
    int tid = threadIdx.x;
    int lane = tid & 31, warp = tid >> 5;
    int b0w = (warp & 3) * 16;          // b quarter
    int j0w = (warp >> 2) * 16;         // j half
    int jt = blockIdx.x, ks = blockIdx.y;
    int j0g = jt * 32;
    int k0g = ks * 1024;

    __shared__ __align__(8) u64 mbar[NSTG];
    u32 sbase = (s2u(SBraw) + 1023) & ~1023u;

    if (tid == 0) {
        #pragma unroll
        for (int s = 0; s < NSTG; s++) MBAR_INIT(s2u(&mbar[s]), 1);
    }
    __syncthreads();

    const CUtensorMap* pH = (t & 1) ? &mH1 : &mH0;
    const CUtensorMap* pL = (t & 1) ? &mL1 : &mL0;

    if (tid == 0) {
        #pragma unroll
        for (int s = 0; s < NSTG; s++) {
            int kx = k0g + s * 64;
            u32 st = sbase + s * STG_BYTES;
            u32 mb = s2u(&mbar[s]);
            MBAR_EXPECT(mb, STG_BYTES);
            TMA2D(st + S_HH, pH, kx, 0, mb);
            TMA2D(st + S_HL, pL, kx, 0, mb);
            TMA2D(st + S_WH, &mWh, kx, j0g, mb);
            TMA2D(st + S_WL, &mWl, kx, j0g, mb);
        }
    }

    float acc[2][4];
    #pragma unroll
    for (int n = 0; n < 2; n++)
        #pragma unroll
        for (int q = 0; q < 4; q++) acc[n][q] = 0.0f;

    int arow = b0w + (lane & 15);
    u32 acb = (u32)(lane >> 4) * 16;
    int brow = j0w + ((lane >> 4) << 3) + (lane & 7);
    u32 bcb = (u32)((lane >> 3) & 1) * 16;

    for (int it = 0; it < 16; it++) {
        int s = it & (NSTG - 1);
        u32 st = sbase + s * STG_BYTES;
        MBAR_WAIT(s2u(&mbar[s]), (it >> 3) & 1);

        #pragma unroll
        for (int kk = 0; kk < 64; kk += 16) {
            u32 aoff = swz((u32)arow * 128 + acb + kk * 2);
            u32 boff = swz((u32)brow * 128 + bcb + kk * 2);
            u32 ahi[4], alo[4], bhi[4], blo[4];
            LDSM4(ahi, st + S_HH + aoff);
            LDSM4(alo, st + S_HL + aoff);
            LDSM4(bhi, st + S_WH + boff);
            LDSM4(blo, st + S_WL + boff);
            #pragma unroll
            for (int n = 0; n < 2; n++) {
                MMA16816(acc[n], ahi, bhi[n * 2], bhi[n * 2 + 1]);
                MMA16816(acc[n], alo, bhi[n * 2], bhi[n * 2 + 1]);
                MMA16816(acc[n], ahi, blo[n * 2], blo[n * 2 + 1]);
            }
        }
        __syncthreads();
        if (it < 8 && tid == 0) {
            int kx = k0g + (it + 8) * 64;
            u32 mb = s2u(&mbar[s]);
            MBAR_EXPECT(mb, STG_BYTES);
            TMA2D(st + S_HH, pH, kx, 0, mb);
            TMA2D(st + S_HL, pL, kx, 0, mb);
            TMA2D(st + S_WH, &mWh, kx, j0g, mb);
            TMA2D(st + S_WL, &mWl, kx, j0g, mb);
        }
    }

    // ---- seed fold (ks==0) + partial write ----
    const float* hin = g_hist + (size_t)t * Bdim * Hdim;
    const float* xp  = g_xp + (size_t)t * Bdim * Hdim;
    int r0 = b0w + (lane >> 2);
    float* P = g_part[ks];
    #pragma unroll
    for (int n = 0; n < 2; n++) {
        int c = j0g + j0w + n * 8 + (lane & 3) * 2;
        size_t i0 = (size_t)r0 * Hdim + c;
        size_t i1 = (size_t)(r0 + 8) * Hdim + c;
        if (ks == 0) {
            acc[n][0] += (1.0f - ALPHA) * hin[i0]     + xp[i0];
            acc[n][1] += (1.0f - ALPHA) * hin[i0 + 1] + xp[i0 + 1];
            acc[n][2] += (1.0f - ALPHA) * hin[i1]     + xp[i1];
            acc[n][3] += (1.0f - ALPHA) * hin[i1 + 1] + xp[i1 + 1];
        }
        float2 v0 = {acc[n][0], acc[n][1]};
        float2 v1 = {acc[n][2], acc[n][3]};
        *(float2*)&P[i0] = v0;
        *(float2*)&P[i1] = v1;
    }

    // ---- last-arriving CTA of the pair finishes in registers ----
    __threadfence();
    __syncthreads();
    __shared__ unsigned s_last;
    if (tid == 0) s_last = (atomicAdd(&g_cnt[jt], 1u) == 1u) ? 1u : 0u;
    __syncthreads();
    if (!s_last) return;
    __threadfence();

    const float* O = g_part[ks ^ 1];
    float* hout = g_hist + (size_t)(t + 1) * Bdim * Hdim;
    u32* HHo = (u32*)g_hh[(t + 1) & 1];
    u32* HLo = (u32*)g_hl[(t + 1) & 1];

    #pragma unroll
    for (int n = 0; n < 2; n++) {
        int c = j0g + j0w + n * 8 + (lane & 3) * 2;
        size_t i0 = (size_t)r0 * Hdim + c;
        size_t i1 = (size_t)(r0 + 8) * Hdim + c;
        float2 o0 = *(const float2*)&O[i0];
        float2 o1 = *(const float2*)&O[i1];
        float2 s0 = {acc[n][0] + o0.x, acc[n][1] + o0.y};
        float2 s1 = {acc[n][2] + o1.x, acc[n][3] + o1.y};
        *(float2*)&hout[i0] = s0;
        *(float2*)&hout[i1] = s1;

        __nv_bfloat16 h0 = __float2bfloat16_rn(s0.x);
        __nv_bfloat16 h1 = __float2bfloat16_rn(s0.y);
        __nv_bfloat16 h2 = __float2bfloat16_rn(s1.x);
        __nv_bfloat16 h3 = __float2bfloat16_rn(s1.y);
        union { __nv_bfloat16 h[2]; u32 u; } p0, p1, l0, l1;
        p0.h[0] = h0; p0.h[1] = h1;
        p1.h[0] = h2; p1.h[1] = h3;
        l0.h[0] = __float2bfloat16_rn(s0.x - __bfloat162float(h0));
        l0.h[1] = __float2bfloat16_rn(s0.y - __bfloat162float(h1));
        l1.h[0] = __float2bfloat16_rn(s1.x - __bfloat162float(h2));
        l1.h[1] = __float2bfloat16_rn(s1.y - __bfloat162float(h3));
        HHo[i0 >> 1] = p0.u; HHo[i1 >> 1] = p1.u;
        HLo[i0 >> 1] = l0.u; HLo[i1 >> 1] = l1.u;
    }

    __syncthreads();
    if (tid == 0) g_cnt[jt] = 0;    // reset for next launch / replay
}

// ---------------------------------------------------------------------------
// out: out[b][t][o] = sum_k hist[t][b][k] * wout[k][o]
// ---------------------------------------------------------------------------
__global__ void out_kernel(const float* __restrict__ wout,
                           float* __restrict__ out) {
    __shared__ float sh[64][68];
    __shared__ float sw[64][68];
    int t  = blockIdx.y;
    int c0 = blockIdx.x * 64;
    int tid = threadIdx.x;
    int tx = tid & 15, ty = tid >> 4;

    u64 acc[4][4];
    #pragma unroll
    for (int i = 0; i < 4; i++)
        #pragma unroll
        for (int j = 0; j < 4; j++) acc[i][j] = 0ull;

    const float* hin = g_hist + (size_t)t * Bdim * Hdim;

    for (int k0 = 0; k0 < Hdim; k0 += 64) {
        #pragma unroll
        for (int i = 0; i < 4; i++) {
            int idx = tid + 256 * i;
            int b = idx >> 4, q = idx & 15;
            *(float4*)&sh[b][q * 4] = *(const float4*)(hin + (size_t)b * Hdim + k0 + q * 4);
        }
        #pragma unroll
        for (int i = 0; i < 4; i++) {
            int idx = tid + 256 * i;
            int kr = idx >> 4, q = idx & 15;
            float4 v = *(const float4*)(wout + ((size_t)(k0 + kr)) * Odim + c0 + q * 4);
            sw[q * 4 + 0][kr] = v.x;
            sw[q * 4 + 1][kr] = v.y;
            sw[q * 4 + 2][kr] = v.z;
            sw[q * 4 + 3][kr] = v.w;
        }
        __syncthreads();
        #pragma unroll
        for (int kb = 0; kb < 64; kb += 2) {
            u64 ha[4], wb[4];
            #pragma unroll
            for (int i = 0; i < 4; i++) ha[i] = *(const u64*)&sh[ty + 16 * i][kb];
            #pragma unroll
            for (int j = 0; j < 4; j++) wb[j] = *(const u64*)&sw[tx + 16 * j][kb];
            #pragma unroll
            for (int i = 0; i < 4; i++)
                #pragma unroll
                for (int j = 0; j < 4; j++)
                    acc[i][j] = ffma2(ha[i], wb[j], acc[i][j]);
        }
        __syncthreads();
    }

    #pragma unroll
    for (int i = 0; i < 4; i++) {
        int b = ty + 16 * i;
        #pragma unroll
        for (int j = 0; j < 4; j++) {
            int o = c0 + tx + 16 * j;
            out[((size_t)b * Sdim + t) * Odim + o] = hsum2(acc[i][j]);
        }
    }
}

// ---------------------------------------------------------------------------
// host: tensormap construction via driver entry point (no -lcuda needed)
// ---------------------------------------------------------------------------
typedef CUresult (*PFN_TMEnc)(CUtensorMap*, CUtensorMapDataType, cuuint32_t,
                              void*, const cuuint64_t*, const cuuint64_t*,
                              const cuuint32_t*, const cuuint32_t*,
                              CUtensorMapInterleave, CUtensorMapSwizzle,
                              CUtensorMapL2promotion, CUtensorMapFloatOOBfill);

static void make_map(PFN_TMEnc enc, CUtensorMap* m, void* base,
                     cuuint64_t d0, cuuint64_t d1, cuuint32_t b0, cuuint32_t b1) {
    cuuint64_t dims[2] = {d0, d1};
    cuuint64_t strides[1] = {d0 * 2};
    cuuint32_t box[2] = {b0, b1};
    cuuint32_t es[2] = {1, 1};
    enc(m, CU_TENSOR_MAP_DATA_TYPE_BFLOAT16, 2, base, dims, strides, box, es,
        CU_TENSOR_MAP_INTERLEAVE_NONE, CU_TENSOR_MAP_SWIZZLE_128B,
        CU_TENSOR_MAP_L2_PROMOTION_L2_128B, CU_TENSOR_MAP_FLOAT_OOB_FILL_NONE);
}

extern "C" void kernel_launch(void* const* d_in, const int* in_sizes, int n_in,
                              void* d_out, int out_size) {
    const float* x     = (const float*)d_in[0];
    const float* noise = (const float*)d_in[1];
    const float* wi    = (const float*)d_in[2];
    const float* wrec  = (const float*)d_in[3];
    const float* wout  = (const float*)d_in[4];
    const float* g     = (const float*)d_in[5];
    const float* h0    = (const float*)d_in[6];
    float* out = (float*)d_out;

    PFN_TMEnc enc = nullptr;
    {
        void* fn = nullptr;
        cudaDriverEntryPointQueryResult qr;
        cudaGetDriverEntryPoint("cuTensorMapEncodeTiled", &fn,
                                cudaEnableDefault, &qr);
        enc = (PFN_TMEnc)fn;
    }

    void *pWh, *pWl, *pHH, *pHL;
    cudaGetSymbolAddress(&pWh, g_Whi);
    cudaGetSymbolAddress(&pWl, g_Wlo);
    cudaGetSymbolAddress(&pHH, g_hh);
    cudaGetSymbolAddress(&pHL, g_hl);
    size_t hbytes = (size_t)Bdim * Hdim * 2;

    CUtensorMap mWh, mWl, mH0, mH1, mL0, mL1;
    make_map(enc, &mWh, pWh, Hdim, Hdim, 64, 32);
    make_map(enc, &mWl, pWl, Hdim, Hdim, 64, 32);
    make_map(enc, &mH0, pHH, Hdim, Bdim, 64, 64);
    make_map(enc, &mH1, (char*)pHH + hbytes, Hdim, Bdim, 64, 64);
    make_map(enc, &mL0, pHL, Hdim, Bdim, 64, 64);
    make_map(enc, &mL1, (char*)pHL + hbytes, Hdim, Bdim, 64, 64);

    cudaFuncSetAttribute(mma_step, cudaFuncAttributeMaxDynamicSharedMemorySize,
                         SMEM_MMA);

    prep_kernel<<<Hdim, 256>>>(wrec, g, h0);
    xp_kernel<<<dim3(Hdim / 64, Sdim - 1), 256>>>(x, noise, wi);
    for (int t = 0; t < Sdim - 1; t++)
        mma_step<<<dim3(64, 2), 256, SMEM_MMA>>>(t, mWh, mWl, mH0, mH1, mL0, mL1);
    out_kernel<<<dim3(Odim / 64, Sdim), 256>>>(wout, out);
}

// round 17
// speedup vs baseline: 3.6359x; 1.1672x over previous
#include <cuda_runtime.h>
#include <cuda.h>
#include <cuda_bf16.h>
#include <cstdint>
#include <cstddef>

#define Bdim 64
#define Sdim 512
#define Idim 128
#define Hdim 2048
#define Odim 128
#define ALPHA 0.2f
#define NSTD  0.005f
#define NCTA  128
#define NSTEP (Sdim - 1)

// ---- device scratch ----
__device__ __align__(1024) __nv_bfloat16 g_Whi[(size_t)Hdim * Hdim];
__device__ __align__(1024) __nv_bfloat16 g_Wlo[(size_t)Hdim * Hdim];
__device__ __align__(1024) __nv_bfloat16 g_hh[2][(size_t)Bdim * Hdim];
__device__ __align__(1024) __nv_bfloat16 g_hl[2][(size_t)Bdim * Hdim];
__device__ float g_hist[(size_t)Sdim * Bdim * Hdim];      // h_t fp32, [t][b][k]
__device__ float g_xp[(size_t)(Sdim - 1) * Bdim * Hdim];  // NSTD*noise + ALPHA*x@wi
__device__ unsigned g_epoch;                              // global step barrier

typedef unsigned long long u64;
typedef unsigned int u32;

__device__ __forceinline__ u64 ffma2(u64 a, u64 b, u64 c) {
    u64 d;
    asm("fma.rn.f32x2 %0, %1, %2, %3;" : "=l"(d) : "l"(a), "l"(b), "l"(c));
    return d;
}
__device__ __forceinline__ float hsum2(u64 a) {
    float2 f = *reinterpret_cast<float2*>(&a);
    return f.x + f.y;
}
__device__ __forceinline__ u32 s2u(const void* p) {
    return (u32)__cvta_generic_to_shared(p);
}
__device__ __forceinline__ u32 swz(u32 off) {           // SW128 swizzle
    return off ^ ((off >> 3) & 0x70);
}

#define LDSM4(R, ADDR)                                                        \
    asm volatile("ldmatrix.sync.aligned.m8n8.x4.shared.b16 {%0,%1,%2,%3},[%4];" \
                 : "=r"((R)[0]), "=r"((R)[1]), "=r"((R)[2]), "=r"((R)[3])     \
                 : "r"(ADDR))

#define MMA16816(C, A, B0, B1)                                                \
    asm volatile("mma.sync.aligned.m16n8k16.row.col.f32.bf16.bf16.f32 "       \
                 "{%0,%1,%2,%3},{%4,%5,%6,%7},{%8,%9},{%0,%1,%2,%3};"         \
                 : "+f"((C)[0]), "+f"((C)[1]), "+f"((C)[2]), "+f"((C)[3])     \
                 : "r"((A)[0]), "r"((A)[1]), "r"((A)[2]), "r"((A)[3]),        \
                   "r"(B0), "r"(B1))

#define MBAR_INIT(A, N) \
    asm volatile("mbarrier.init.shared.b64 [%0], %1;" :: "r"(A), "r"(N) : "memory")
#define MBAR_EXPECT(A, B) \
    asm volatile("mbarrier.arrive.expect_tx.shared.b64 _, [%0], %1;" :: "r"(A), "r"(B) : "memory")
#define MBAR_WAIT(A, PH) do {                                                 \
    asm volatile(                                                             \
        "{\n\t.reg .pred P1;\n\t"                                             \
        "WAIT_LOOP_%=:\n\t"                                                   \
        "mbarrier.try_wait.parity.acquire.cta.shared::cta.b64 P1, [%0], %1, 0x989680;\n\t" \
        "@P1 bra.uni WAIT_DONE_%=;\n\t"                                       \
        "bra.uni WAIT_LOOP_%=;\n\t"                                           \
        "WAIT_DONE_%=:\n\t}"                                                  \
        :: "r"(A), "r"(PH) : "memory");                                       \
} while (0)

#define TMA2D(SMEM, MAP, X, Y, MB)                                            \
    asm volatile("cp.async.bulk.tensor.2d.shared::cta.global.tile"            \
                 ".mbarrier::complete_tx::bytes [%0], [%1, {%2, %3}], [%4];"  \
                 :: "r"(SMEM), "l"(MAP), "r"(X), "r"(Y), "r"(MB) : "memory")

// ---------------------------------------------------------------------------
// prep: Whi/Wlo from ALPHA*g*wrec; init hist[0], hh[0], hl[0]; epoch=0
// ---------------------------------------------------------------------------
__global__ void prep_kernel(const float* __restrict__ wrec,
                            const float* __restrict__ g,
                            const float* __restrict__ h0) {
    int j = blockIdx.x;
    for (int k = threadIdx.x; k < Hdim; k += blockDim.x) {
        float w = ALPHA * g[k] * wrec[(size_t)j * Hdim + k];
        __nv_bfloat16 wh = __float2bfloat16_rn(w);
        g_Whi[(size_t)j * Hdim + k] = wh;
        g_Wlo[(size_t)j * Hdim + k] = __float2bfloat16_rn(w - __bfloat162float(wh));
    }
    if (j < Bdim) {
        for (int k = threadIdx.x; k < Hdim; k += blockDim.x) {
            float h = h0[k];
            g_hist[(size_t)j * Hdim + k] = h;
            __nv_bfloat16 hh = __float2bfloat16_rn(h);
            g_hh[0][(size_t)j * Hdim + k] = hh;
            g_hl[0][(size_t)j * Hdim + k] = __float2bfloat16_rn(h - __bfloat162float(hh));
        }
    }
    if (blockIdx.x == 0 && threadIdx.x == 0) g_epoch = 0;
}

// ---------------------------------------------------------------------------
// xp: xp[t][b][j] = NSTD*noise[b][t][j] + ALPHA * sum_i x[b][t][i]*wi[i][j]
// ---------------------------------------------------------------------------
__global__ void xp_kernel(const float* __restrict__ x,
                          const float* __restrict__ noise,
                          const float* __restrict__ wi) {
    __shared__ float sx[64][68];
    __shared__ float sw[64][68];
    int t  = blockIdx.y;
    int c0 = blockIdx.x * 64;
    int tid = threadIdx.x;
    int tx = tid & 15, ty = tid >> 4;

    u64 acc[4][4];
    #pragma unroll
    for (int i = 0; i < 4; i++)
        #pragma unroll
        for (int j = 0; j < 4; j++) acc[i][j] = 0ull;

    for (int k0 = 0; k0 < Idim; k0 += 64) {
        #pragma unroll
        for (int i = 0; i < 4; i++) {
            int idx = tid + 256 * i;
            int b = idx >> 4, q = idx & 15;
            float4 v = *(const float4*)(x + ((size_t)b * Sdim + t) * Idim + k0 + q * 4);
            *(float4*)&sx[b][q * 4] = v;
        }
        #pragma unroll
        for (int i = 0; i < 4; i++) {
            int idx = tid + 256 * i;
            int kr = idx >> 4, q = idx & 15;
            float4 v = *(const float4*)(wi + ((size_t)(k0 + kr)) * Hdim + c0 + q * 4);
            sw[q * 4 + 0][kr] = v.x;
            sw[q * 4 + 1][kr] = v.y;
            sw[q * 4 + 2][kr] = v.z;
            sw[q * 4 + 3][kr] = v.w;
        }
        __syncthreads();
        #pragma unroll
        for (int kb = 0; kb < 64; kb += 2) {
            u64 ha[4], wb[4];
            #pragma unroll
            for (int i = 0; i < 4; i++) ha[i] = *(const u64*)&sx[ty + 16 * i][kb];
            #pragma unroll
            for (int j = 0; j < 4; j++) wb[j] = *(const u64*)&sw[tx + 16 * j][kb];
            #pragma unroll
            for (int i = 0; i < 4; i++)
                #pragma unroll
                for (int j = 0; j < 4; j++)
                    acc[i][j] = ffma2(ha[i], wb[j], acc[i][j]);
        }
        __syncthreads();
    }

    #pragma unroll
    for (int i = 0; i < 4; i++) {
        int b = ty + 16 * i;
        #pragma unroll
        for (int j = 0; j < 4; j++) {
            int jc = c0 + tx + 16 * j;
            float s = hsum2(acc[i][j]);
            float n = noise[((size_t)b * Sdim + t) * Hdim + jc];
            g_xp[((size_t)t * Bdim + b) * Hdim + jc] = NSTD * n + ALPHA * s;
        }
    }
}

// ---------------------------------------------------------------------------
// persistent RNN kernel: 128 CTAs, CTA = 16 j-cols, full K=2048, all 511 steps.
// W tile (hi+lo, 128KB) resident in smem for the whole kernel (loaded once).
// h streamed per step via 3-slot TMA ring (k=128 stages, 32KB each).
// 8 warps = 4 b-quarters x 2 k-halves; pair-reduce via smem; h_prev in regs.
// Global epoch barrier between steps.
// ---------------------------------------------------------------------------
#define SLOT_BYTES 32768
#define NSLOT 3
#define WOFF_HI (NSLOT * SLOT_BYTES)            // 98304
#define WOFF_LO (WOFF_HI + 65536)               // 163840
#define SMEM_P  (WOFF_LO + 65536 + 1024)        // 230400

extern __shared__ __align__(1024) char SBraw[];

__device__ __forceinline__ void issue_stage(u32 sbase, int slot, int s,
                                            const CUtensorMap* pH,
                                            const CUtensorMap* pL, u32 mb) {
    u32 st = sbase + slot * SLOT_BYTES;
    MBAR_EXPECT(mb, SLOT_BYTES);
    TMA2D(st,         pH, s * 128,      0, mb);
    TMA2D(st + 8192,  pH, s * 128 + 64, 0, mb);
    TMA2D(st + 16384, pL, s * 128,      0, mb);
    TMA2D(st + 24576, pL, s * 128 + 64, 0, mb);
}

__global__ void __launch_bounds__(256, 1) rnn_persist(
    const __grid_constant__ CUtensorMap mWh,
    const __grid_constant__ CUtensorMap mWl,
    const __grid_constant__ CUtensorMap mH0,
    const __grid_constant__ CUtensorMap mH1,
    const __grid_constant__ CUtensorMap mL0,
    const __grid_constant__ CUtensorMap mL1) {
    int tid = threadIdx.x;
    int lane = tid & 31, warp = tid >> 5;
    int wb = warp & 3;                  // b quarter
    int kh = warp >> 2;                 // k half (block within stage)
    int b0w = wb * 16;
    int jt = blockIdx.x;
    int j0g = jt * 16;

    __shared__ __align__(8) u64 mbar[NSLOT + 1];
    u32 sbase = (s2u(SBraw) + 1023) & ~1023u;
    char* sgen = SBraw + (int)(sbase - s2u(SBraw));   // generic ptr to aligned base

    if (tid == 0) {
        #pragma unroll
        for (int s = 0; s < NSLOT + 1; s++) MBAR_INIT(s2u(&mbar[s]), 1);
    }
    __syncthreads();

    // ---- one-time W load (32 blocks of 16x64, hi+lo) ----
    if (tid == 0) {
        u32 wmb = s2u(&mbar[NSLOT]);
        MBAR_EXPECT(wmb, 131072);
        #pragma unroll 4
        for (int blk = 0; blk < 32; blk++) {
            TMA2D(sbase + WOFF_HI + blk * 2048, &mWh, blk * 64, j0g, wmb);
            TMA2D(sbase + WOFF_LO + blk * 2048, &mWl, blk * 64, j0g, wmb);
        }
    }

    // fragment geometry
    int arow = b0w + (lane & 15);
    u32 acb = (u32)(lane >> 4) * 16;
    int brow = ((lane >> 4) << 3) + (lane & 7);
    u32 bcb = (u32)((lane >> 3) & 1) * 16;
    int r0 = b0w + (lane >> 2);

    // h_prev registers (kh==0 warps)
    float hp[2][4];
    if (kh == 0) {
        #pragma unroll
        for (int n = 0; n < 2; n++) {
            int c = j0g + n * 8 + (lane & 3) * 2;
            float2 a = *(const float2*)&g_hist[(size_t)r0 * Hdim + c];
            float2 b = *(const float2*)&g_hist[(size_t)(r0 + 8) * Hdim + c];
            hp[n][0] = a.x; hp[n][1] = a.y; hp[n][2] = b.x; hp[n][3] = b.y;
        }
    }

    MBAR_WAIT(s2u(&mbar[NSLOT]), 0);    // W resident
    __syncthreads();

    float* red = (float*)sgen;          // 4KB reduction scratch (aliases slot 0)

    for (int t = 0; t < NSTEP; t++) {
        const CUtensorMap* pH = (t & 1) ? &mH1 : &mH0;
        const CUtensorMap* pL = (t & 1) ? &mL1 : &mL0;

        if (tid == 0) {
            issue_stage(sbase, 0, 0, pH, pL, s2u(&mbar[0]));
            issue_stage(sbase, 1, 1, pH, pL, s2u(&mbar[1]));
            issue_stage(sbase, 2, 2, pH, pL, s2u(&mbar[2]));
        }

        float accA[2][4], accB[2][4];
        #pragma unroll
        for (int n = 0; n < 2; n++)
            #pragma unroll
            for (int q = 0; q < 4; q++) { accA[n][q] = 0.0f; accB[n][q] = 0.0f; }

        for (int s = 0; s < 16; s++) {
            int sl = s % 3;
            int occ = s / 3;
            int ph = ((sl == 0) ? occ : (t + occ)) & 1;
            MBAR_WAIT(s2u(&mbar[sl]), ph);

            u32 st  = sbase + sl * SLOT_BYTES;
            u32 hhb = st + (u32)kh * 8192;
            u32 hlb = st + 16384 + (u32)kh * 8192;
            u32 whb = sbase + WOFF_HI + (u32)(s * 2 + kh) * 2048;
            u32 wlb = sbase + WOFF_LO + (u32)(s * 2 + kh) * 2048;

            #pragma unroll
            for (int kk = 0; kk < 64; kk += 16) {
                u32 aoff = swz((u32)arow * 128 + acb + kk * 2);
                u32 boff = swz((u32)brow * 128 + bcb + kk * 2);
                u32 ahi[4], alo[4], bhi[4], blo[4];
                LDSM4(ahi, hhb + aoff);
                LDSM4(alo, hlb + aoff);
                LDSM4(bhi, whb + boff);
                LDSM4(blo, wlb + boff);
                #pragma unroll
                for (int n = 0; n < 2; n++) {
                    MMA16816(accA[n], ahi, bhi[n * 2], bhi[n * 2 + 1]);
                    MMA16816(accB[n], alo, bhi[n * 2], bhi[n * 2 + 1]);
                    MMA16816(accB[n], ahi, blo[n * 2], blo[n * 2 + 1]);
                }
            }
            __syncthreads();
            if (s < 13 && tid == 0)
                issue_stage(sbase, sl, s + 3, pH, pL, s2u(&mbar[sl]));
        }

        // merge 3-product accumulators
        float res[2][4];
        #pragma unroll
        for (int n = 0; n < 2; n++)
            #pragma unroll
            for (int q = 0; q < 4; q++) res[n][q] = accA[n][q] + accB[n][q];

        // cross-warp k-reduction (kh pairs) via smem
        if (kh == 1) {
            #pragma unroll
            for (int n = 0; n < 2; n++)
                #pragma unroll
                for (int q = 0; q < 4; q++)
                    red[wb * 256 + lane * 8 + n * 4 + q] = res[n][q];
        }
        __syncthreads();

        if (kh == 0) {
            const float* xp = g_xp + (size_t)t * Bdim * Hdim;
            float* hout = g_hist + (size_t)(t + 1) * Bdim * Hdim;
            u32* HHo = (u32*)g_hh[(t + 1) & 1];
            u32* HLo = (u32*)g_hl[(t + 1) & 1];
            #pragma unroll
            for (int n = 0; n < 2; n++) {
                int c = j0g + n * 8 + (lane & 3) * 2;
                size_t i0 = (size_t)r0 * Hdim + c;
                size_t i1 = (size_t)(r0 + 8) * Hdim + c;
                float2 xv0 = *(const float2*)&xp[i0];
                float2 xv1 = *(const float2*)&xp[i1];
                float p0 = red[wb * 256 + lane * 8 + n * 4 + 0];
                float p1 = red[wb * 256 + lane * 8 + n * 4 + 1];
                float p2 = red[wb * 256 + lane * 8 + n * 4 + 2];
                float p3 = red[wb * 256 + lane * 8 + n * 4 + 3];
                float2 s0, s1;
                s0.x = res[n][0] + p0 + (1.0f - ALPHA) * hp[n][0] + xv0.x;
                s0.y = res[n][1] + p1 + (1.0f - ALPHA) * hp[n][1] + xv0.y;
                s1.x = res[n][2] + p2 + (1.0f - ALPHA) * hp[n][2] + xv1.x;
                s1.y = res[n][3] + p3 + (1.0f - ALPHA) * hp[n][3] + xv1.y;
                hp[n][0] = s0.x; hp[n][1] = s0.y; hp[n][2] = s1.x; hp[n][3] = s1.y;
                *(float2*)&hout[i0] = s0;
                *(float2*)&hout[i1] = s1;

                __nv_bfloat16 h0 = __float2bfloat16_rn(s0.x);
                __nv_bfloat16 h1 = __float2bfloat16_rn(s0.y);
                __nv_bfloat16 h2 = __float2bfloat16_rn(s1.x);
                __nv_bfloat16 h3 = __float2bfloat16_rn(s1.y);
                union { __nv_bfloat16 h[2]; u32 u; } q0, q1, l0, l1;
                q0.h[0] = h0; q0.h[1] = h1;
                q1.h[0] = h2; q1.h[1] = h3;
                l0.h[0] = __float2bfloat16_rn(s0.x - __bfloat162float(h0));
                l0.h[1] = __float2bfloat16_rn(s0.y - __bfloat162float(h1));
                l1.h[0] = __float2bfloat16_rn(s1.x - __bfloat162float(h2));
                l1.h[1] = __float2bfloat16_rn(s1.y - __bfloat162float(h3));
                HHo[i0 >> 1] = q0.u; HHo[i1 >> 1] = q1.u;
                HLo[i0 >> 1] = l0.u; HLo[i1 >> 1] = l1.u;
            }
        }

        if (t == NSTEP - 1) break;      // no barrier after last step

        // ---- device-wide step barrier ----
        __threadfence();
        __syncthreads();
        if (tid == 0) {
            atomicAdd(&g_epoch, 1u);
            unsigned target = (unsigned)NCTA * (unsigned)(t + 1);
            volatile unsigned* ep = &g_epoch;
            while (*ep < target) __nanosleep(64);
            __threadfence();
            asm volatile("fence.proxy.async;" ::: "memory");
        }
        __syncthreads();
    }
}

// ---------------------------------------------------------------------------
// out: out[b][t][o] = sum_k hist[t][b][k] * wout[k][o]
// ---------------------------------------------------------------------------
__global__ void out_kernel(const float* __restrict__ wout,
                           float* __restrict__ out) {
    __shared__ float sh[64][68];
    __shared__ float sw[64][68];
    int t  = blockIdx.y;
    int c0 = blockIdx.x * 64;
    int tid = threadIdx.x;
    int tx = tid & 15, ty = tid >> 4;

    u64 acc[4][4];
    #pragma unroll
    for (int i = 0; i < 4; i++)
        #pragma unroll
        for (int j = 0; j < 4; j++) acc[i][j] = 0ull;

    const float* hin = g_hist + (size_t)t * Bdim * Hdim;

    for (int k0 = 0; k0 < Hdim; k0 += 64) {
        #pragma unroll
        for (int i = 0; i < 4; i++) {
            int idx = tid + 256 * i;
            int b = idx >> 4, q = idx & 15;
            *(float4*)&sh[b][q * 4] = *(const float4*)(hin + (size_t)b * Hdim + k0 + q * 4);
        }
        #pragma unroll
        for (int i = 0; i < 4; i++) {
            int idx = tid + 256 * i;
            int kr = idx >> 4, q = idx & 15;
            float4 v = *(const float4*)(wout + ((size_t)(k0 + kr)) * Odim + c0 + q * 4);
            sw[q * 4 + 0][kr] = v.x;
            sw[q * 4 + 1][kr] = v.y;
            sw[q * 4 + 2][kr] = v.z;
            sw[q * 4 + 3][kr] = v.w;
        }
        __syncthreads();
        #pragma unroll
        for (int kb = 0; kb < 64; kb += 2) {
            u64 ha[4], wb[4];
            #pragma unroll
            for (int i = 0; i < 4; i++) ha[i] = *(const u64*)&sh[ty + 16 * i][kb];
            #pragma unroll
            for (int j = 0; j < 4; j++) wb[j] = *(const u64*)&sw[tx + 16 * j][kb];
            #pragma unroll
            for (int i = 0; i < 4; i++)
                #pragma unroll
                for (int j = 0; j < 4; j++)
                    acc[i][j] = ffma2(ha[i], wb[j], acc[i][j]);
        }
        __syncthreads();
    }

    #pragma unroll
    for (int i = 0; i < 4; i++) {
        int b = ty + 16 * i;
        #pragma unroll
        for (int j = 0; j < 4; j++) {
            int o = c0 + tx + 16 * j;
            out[((size_t)b * Sdim + t) * Odim + o] = hsum2(acc[i][j]);
        }
    }
}

// ---------------------------------------------------------------------------
// host: tensormap construction via driver entry point (no -lcuda needed)
// ---------------------------------------------------------------------------
typedef CUresult (*PFN_TMEnc)(CUtensorMap*, CUtensorMapDataType, cuuint32_t,
                              void*, const cuuint64_t*, const cuuint64_t*,
                              const cuuint32_t*, const cuuint32_t*,
                              CUtensorMapInterleave, CUtensorMapSwizzle,
                              CUtensorMapL2promotion, CUtensorMapFloatOOBfill);

static void make_map(PFN_TMEnc enc, CUtensorMap* m, void* base,
                     cuuint64_t d0, cuuint64_t d1, cuuint32_t b0, cuuint32_t b1) {
    cuuint64_t dims[2] = {d0, d1};
    cuuint64_t strides[1] = {d0 * 2};
    cuuint32_t box[2] = {b0, b1};
    cuuint32_t es[2] = {1, 1};
    enc(m, CU_TENSOR_MAP_DATA_TYPE_BFLOAT16, 2, base, dims, strides, box, es,
        CU_TENSOR_MAP_INTERLEAVE_NONE, CU_TENSOR_MAP_SWIZZLE_128B,
        CU_TENSOR_MAP_L2_PROMOTION_L2_128B, CU_TENSOR_MAP_FLOAT_OOB_FILL_NONE);
}

extern "C" void kernel_launch(void* const* d_in, const int* in_sizes, int n_in,
                              void* d_out, int out_size) {
    const float* x     = (const float*)d_in[0];
    const float* noise = (const float*)d_in[1];
    const float* wi    = (const float*)d_in[2];
    const float* wrec  = (const float*)d_in[3];
    const float* wout  = (const float*)d_in[4];
    const float* g     = (const float*)d_in[5];
    const float* h0    = (const float*)d_in[6];
    float* out = (float*)d_out;

    PFN_TMEnc enc = nullptr;
    {
        void* fn = nullptr;
        cudaDriverEntryPointQueryResult qr;
        cudaGetDriverEntryPoint("cuTensorMapEncodeTiled", &fn,
                                cudaEnableDefault, &qr);
        enc = (PFN_TMEnc)fn;
    }

    void *pWh, *pWl, *pHH, *pHL;
    cudaGetSymbolAddress(&pWh, g_Whi);
    cudaGetSymbolAddress(&pWl, g_Wlo);
    cudaGetSymbolAddress(&pHH, g_hh);
    cudaGetSymbolAddress(&pHL, g_hl);
    size_t hbytes = (size_t)Bdim * Hdim * 2;

    CUtensorMap mWh, mWl, mH0, mH1, mL0, mL1;
    make_map(enc, &mWh, pWh, Hdim, Hdim, 64, 16);
    make_map(enc, &mWl, pWl, Hdim, Hdim, 64, 16);
    make_map(enc, &mH0, pHH, Hdim, Bdim, 64, 64);
    make_map(enc, &mH1, (char*)pHH + hbytes, Hdim, Bdim, 64, 64);
    make_map(enc, &mL0, pHL, Hdim, Bdim, 64, 64);
    make_map(enc, &mL1, (char*)pHL + hbytes, Hdim, Bdim, 64, 64);

    cudaFuncSetAttribute(rnn_persist, cudaFuncAttributeMaxDynamicSharedMemorySize,
                         SMEM_P);

    prep_kernel<<<Hdim, 256>>>(wrec, g, h0);
    xp_kernel<<<dim3(Hdim / 64, Sdim - 1), 256>>>(x, noise, wi);
    rnn_persist<<<NCTA, 256, SMEM_P>>>(mWh, mWl, mH0, mH1, mL0, mL1);
    out_kernel<<<dim3(Odim / 64, Sdim), 256>>>(wout, out);
}